// round 9
// baseline (speedup 1.0000x reference)
#include <cuda_runtime.h>
#include <math.h>
#include <stdint.h>

// ---------------------------------------------------------------------------
// Problem constants: B=4, S=1024, E=1024, H=16, DH=64
// ---------------------------------------------------------------------------
#define BB   4
#define SS   1024
#define EE   1024
#define HH   16
#define DH   64
#define NTOK (BB * SS)          // 4096 rows

// ---------------------------------------------------------------------------
// Scratch (static device globals; no allocation allowed anywhere)
// ---------------------------------------------------------------------------
__device__ float g_h    [(size_t)NTOK * EE];
__device__ float g_qkv  [(size_t)NTOK * 3 * EE];
__device__ float g_probs[(size_t)BB * HH * SS * SS];   // unnormalized exp scores (tf32-rounded)
__device__ float g_att  [(size_t)NTOK * EE];
__device__ float g_x1   [(size_t)NTOK * EE];
__device__ float g_h2   [(size_t)NTOK * EE];
__device__ float g_fc   [(size_t)NTOK * 4 * EE];
__device__ float g_psum [(size_t)BB * HH * SS * 8];    // per-tile partial row sums
__device__ float g_rsum [(size_t)BB * HH * SS];        // row sums of exp scores
__device__ float g_w    [(size_t)12 * 1024 * 1024];    // tf32-rounded weights

// g_w offsets (floats)
#define WOFF_IN   0L
#define WOFF_OUT  (3L * 1024 * 1024)
#define WOFF_FC   (4L * 1024 * 1024)
#define WOFF_PROJ (8L * 1024 * 1024)

__device__ __forceinline__ float* scratch_ptr(int id) {
    switch (id) {
        case 0:  return g_h;
        case 1:  return g_qkv;
        case 2:  return g_probs;
        case 3:  return g_att;
        case 4:  return g_x1;
        case 5:  return g_h2;
        case 7:  return g_w;
        default: return g_fc;
    }
}
__device__ __forceinline__ const float* resolve_c(const float* ext, int id, long off) {
    return (id >= 0 ? (const float*)scratch_ptr(id) : ext) + off;
}
__device__ __forceinline__ float* resolve_m(float* ext, int id) {
    return id >= 0 ? scratch_ptr(id) : ext;
}

__device__ __forceinline__ float gelu_f(float v) {
    const float c = 0.7978845608028654f;
    float t = tanhf(c * (v + 0.044715f * v * v * v));
    return 0.5f * v * (1.f + t);
}

__device__ __forceinline__ uint32_t f2tf32(float f) {
    uint32_t u;
    asm("cvt.rna.tf32.f32 %0, %1;" : "=r"(u) : "f"(f));
    return u;
}
__device__ __forceinline__ float rnd_tf32(float f) {
    return __uint_as_float(f2tf32(f));
}

__device__ __forceinline__ void mma_tf32(float* c, const uint32_t* a, const uint32_t* b) {
    asm volatile(
        "mma.sync.aligned.m16n8k8.row.col.f32.tf32.tf32.f32 "
        "{%0,%1,%2,%3}, {%4,%5,%6,%7}, {%8,%9}, {%0,%1,%2,%3};"
        : "+f"(c[0]), "+f"(c[1]), "+f"(c[2]), "+f"(c[3])
        : "r"(a[0]), "r"(a[1]), "r"(a[2]), "r"(a[3]), "r"(b[0]), "r"(b[1]));
}

__device__ __forceinline__ void cp16(void* dst, const void* src) {
    uint32_t d = (uint32_t)__cvta_generic_to_shared(dst);
    asm volatile("cp.async.ca.shared.global [%0], [%1], 16;\n" :: "r"(d), "l"(src));
}
__device__ __forceinline__ void cp_commit() {
    asm volatile("cp.async.commit_group;\n");
}
template <int N>
__device__ __forceinline__ void cp_wait() {
    asm volatile("cp.async.wait_group %0;\n" :: "n"(N));
}

enum { EPI_NONE = 0, EPI_BIAS = 1, EPI_BIAS_RES = 2, EPI_GELU = 3, EPI_EXP = 4, EPI_PV = 5 };

// ---------------------------------------------------------------------------
// tf32 tensor-core GEMM, cp.async double buffered, NO in-loop conversion
// (all operands pre-rounded to tf32 at production time).
//   B_NT=true : B stored [N,K] row-major (C = A * B^T)
//   B_NT=false: B stored [K,N] row-major (C = A * B)
// CTA swizzle: groups of 8 M-tiles iterate N fastest for L2 reuse.
// EPI_EXP: p = rnd(exp(scale*s)) masked causal + per-tile partial row sums;
//          fully-masked tiles exit immediately.
// EPI_PV : divide by g_rsum[row], TRI_K truncation, rounded output.
// ---------------------------------------------------------------------------
template <int BM, int BN, int WARPS_M, int WARPS_N, int EPI, bool B_NT, bool TRI_K>
__global__ __launch_bounds__(256, 2)
void mma_gemm(const float* __restrict__ Ax, int Aid, long Aoff,
              const float* __restrict__ Bx, int Bid, long Boff,
              float* __restrict__ Cx, int Cid,
              int K, int lda, int ldb, int ldc,
              const float* __restrict__ bias,
              const float* __restrict__ Rx, int Rid, int ldres,
              long aOuter, long aInner, long bOuter, long bInner,
              long cOuter, long cInner, int Hdim, float scale)
{
    constexpr int BK  = 16;
    constexpr int AKP = BK + 4;
    constexpr int WM = BM / WARPS_M, WN = BN / WARPS_N;
    constexpr int MF = WM / 16, NF = WN / 8;
    constexpr int BD1 = B_NT ? BN : BK;
    constexpr int BD2 = B_NT ? AKP : (BN + 8);
    constexpr int RP1 = (EPI == EPI_EXP) ? WARPS_N : 1;
    constexpr int RP2 = (EPI == EPI_EXP) ? BM : 1;

    // ---- CTA swizzle: 8 M-tiles per group, N fastest within group ----
    int Mt = gridDim.y, Nt = gridDim.x;
    int linear = blockIdx.y * Nt + blockIdx.x;
    int tpg = 8 * Nt;
    int grp = linear / tpg;
    int rem = linear - grp * tpg;
    int gm = grp * 8;
    int rows = min(8, Mt - gm);
    int mIdx = gm + rem % rows;
    int nIdx = rem / rows;
    int bm = mIdx * BM, bn = nIdx * BN;

    if (EPI == EPI_EXP && bn >= bm + BM) return;    // fully masked: nothing to do

    const float* A = resolve_c(Ax, Aid, Aoff);
    const float* B = resolve_c(Bx, Bid, Boff);
    float*       C = resolve_m(Cx, Cid);

    int z  = blockIdx.z;
    int zo = z / Hdim, zi = z - zo * Hdim;
    A += (size_t)zo * aOuter + (size_t)zi * aInner;
    B += (size_t)zo * bOuter + (size_t)zi * bInner;
    C += (size_t)zo * cOuter + (size_t)zi * cInner;

    __shared__ __align__(16) float As[2][BM][AKP];
    __shared__ __align__(16) float Bs[2][BD1][BD2];
    __shared__ float rowp[RP1][RP2];

    int tid  = threadIdx.x;
    int wid  = tid >> 5, lane = tid & 31;
    int g    = lane >> 2, tig = lane & 3;
    int wm   = (wid / WARPS_N) * WM;
    int wn   = (wid % WARPS_N) * WN;
    int wnIdx = wid % WARPS_N;

    const float* Ag = A + (size_t)bm * lda;
    const float* Bg = B_NT ? (B + (size_t)bn * ldb) : B;

    int Kend = TRI_K ? min(K, bm + BM) : K;
    int T = Kend / BK;

    float acc[MF][NF][4] = {};

    auto loadA = [&](int st, int k0) {
#pragma unroll
        for (int i = 0; i < BM / 64; i++) {
            int c = tid + i * 256;
            int m = c >> 2, k4 = c & 3;
            cp16(&As[st][m][k4 * 4], Ag + (size_t)m * lda + k0 + k4 * 4);
        }
    };
    auto loadB = [&](int st, int k0) {
        if (B_NT) {
#pragma unroll
            for (int i = 0; i < BN / 64; i++) {
                int c = tid + i * 256;
                int n = c >> 2, k4 = c & 3;
                cp16(&Bs[st][n][k4 * 4], Bg + (size_t)n * ldb + k0 + k4 * 4);
            }
        } else {
            constexpr int CPR = BN / 4;
#pragma unroll
            for (int i = 0; i < BN / 64; i++) {
                int c = tid + i * 256;
                int k = c / CPR, n4 = c % CPR;
                cp16(&Bs[st][k][n4 * 4], B + (size_t)(k0 + k) * ldb + bn + n4 * 4);
            }
        }
    };

    loadA(0, 0); loadB(0, 0); cp_commit();

    int buf = 0;
    for (int it = 0; it < T; it++) {
        if (it + 1 < T) {
            loadA(buf ^ 1, (it + 1) * BK);
            loadB(buf ^ 1, (it + 1) * BK);
            cp_commit();
            cp_wait<1>();
        } else {
            cp_wait<0>();
        }
        __syncthreads();

#pragma unroll
        for (int kk = 0; kk < BK; kk += 8) {
            uint32_t af[MF][4], bf[NF][2];
#pragma unroll
            for (int mf = 0; mf < MF; mf++) {
                int mb = wm + mf * 16 + g;
                af[mf][0] = __float_as_uint(As[buf][mb    ][kk + tig    ]);
                af[mf][1] = __float_as_uint(As[buf][mb + 8][kk + tig    ]);
                af[mf][2] = __float_as_uint(As[buf][mb    ][kk + tig + 4]);
                af[mf][3] = __float_as_uint(As[buf][mb + 8][kk + tig + 4]);
            }
#pragma unroll
            for (int nf = 0; nf < NF; nf++) {
                int nb = wn + nf * 8 + g;
                if (B_NT) {
                    bf[nf][0] = __float_as_uint(Bs[buf][nb][kk + tig    ]);
                    bf[nf][1] = __float_as_uint(Bs[buf][nb][kk + tig + 4]);
                } else {
                    bf[nf][0] = __float_as_uint(Bs[buf][kk + tig    ][nb]);
                    bf[nf][1] = __float_as_uint(Bs[buf][kk + tig + 4][nb]);
                }
            }
#pragma unroll
            for (int mf = 0; mf < MF; mf++)
#pragma unroll
                for (int nf = 0; nf < NF; nf++)
                    mma_tf32(acc[mf][nf], af[mf], bf[nf]);
        }
        __syncthreads();
        buf ^= 1;
    }

    // ---- epilogue ----
    const float* R = (EPI == EPI_BIAS_RES) ? resolve_c(Rx, Rid, 0) : nullptr;

    float s0[MF], s1[MF];
    if (EPI == EPI_EXP) {
#pragma unroll
        for (int mf = 0; mf < MF; mf++) { s0[mf] = 0.f; s1[mf] = 0.f; }
    }

#pragma unroll
    for (int mf = 0; mf < MF; mf++) {
#pragma unroll
        for (int nf = 0; nf < NF; nf++) {
            int r0 = bm + wm + mf * 16 + g;
            int r1 = r0 + 8;
            int c  = bn + wn + nf * 8 + tig * 2;
            float v0 = acc[mf][nf][0], v1 = acc[mf][nf][1];
            float v2 = acc[mf][nf][2], v3 = acc[mf][nf][3];
            if (EPI == EPI_BIAS || EPI == EPI_BIAS_RES || EPI == EPI_GELU) {
                float b0 = bias[c], b1 = bias[c + 1];
                v0 += b0; v1 += b1; v2 += b0; v3 += b1;
            }
            if (EPI == EPI_BIAS) {          // output feeds GEMMs only -> round
                v0 = rnd_tf32(v0); v1 = rnd_tf32(v1);
                v2 = rnd_tf32(v2); v3 = rnd_tf32(v3);
            }
            if (EPI == EPI_BIAS_RES) {
                float2 ra = *(const float2*)(R + (size_t)r0 * ldres + c);
                float2 rb = *(const float2*)(R + (size_t)r1 * ldres + c);
                v0 += ra.x; v1 += ra.y; v2 += rb.x; v3 += rb.y;
            }
            if (EPI == EPI_GELU) {          // feeds proj GEMM -> round
                v0 = rnd_tf32(gelu_f(v0)); v1 = rnd_tf32(gelu_f(v1));
                v2 = rnd_tf32(gelu_f(v2)); v3 = rnd_tf32(gelu_f(v3));
            }
            if (EPI == EPI_EXP) {           // feeds PV GEMM + mean -> round
                v0 = (c     <= r0) ? rnd_tf32(__expf(v0 * scale)) : 0.f;
                v1 = (c + 1 <= r0) ? rnd_tf32(__expf(v1 * scale)) : 0.f;
                v2 = (c     <= r1) ? rnd_tf32(__expf(v2 * scale)) : 0.f;
                v3 = (c + 1 <= r1) ? rnd_tf32(__expf(v3 * scale)) : 0.f;
                s0[mf] += v0 + v1;
                s1[mf] += v2 + v3;
            }
            if (EPI == EPI_PV) {            // feeds attn-proj GEMM -> round
                float i0 = 1.f / g_rsum[(size_t)z * SS + r0];
                float i1 = 1.f / g_rsum[(size_t)z * SS + r1];
                v0 = rnd_tf32(v0 * i0); v1 = rnd_tf32(v1 * i0);
                v2 = rnd_tf32(v2 * i1); v3 = rnd_tf32(v3 * i1);
            }
            float2 oa = {v0, v1}, ob = {v2, v3};
            *(float2*)(C + (size_t)r0 * ldc + c) = oa;
            *(float2*)(C + (size_t)r1 * ldc + c) = ob;
        }
    }

    if (EPI == EPI_EXP) {
#pragma unroll
        for (int mf = 0; mf < MF; mf++) {
            s0[mf] += __shfl_xor_sync(0xffffffffu, s0[mf], 1);
            s0[mf] += __shfl_xor_sync(0xffffffffu, s0[mf], 2);
            s1[mf] += __shfl_xor_sync(0xffffffffu, s1[mf], 1);
            s1[mf] += __shfl_xor_sync(0xffffffffu, s1[mf], 2);
            if (tig == 0) {
                rowp[wnIdx][wm + mf * 16 + g    ] = s0[mf];
                rowp[wnIdx][wm + mf * 16 + g + 8] = s1[mf];
            }
        }
        __syncthreads();
        if (tid < BM) {
            float t = 0.f;
#pragma unroll
            for (int w = 0; w < WARPS_N; w++) t += rowp[w][tid];
            g_psum[((size_t)z * SS + bm + tid) * 8 + nIdx] = t;
        }
    }
}

// ---------------------------------------------------------------------------
// Round fp32 weights to tf32-in-fp32 into g_w.
// ---------------------------------------------------------------------------
__global__ __launch_bounds__(256)
void round_w_kernel(const float* __restrict__ src, long dstOff, int n4)
{
    int i = blockIdx.x * 256 + threadIdx.x;
    if (i < n4) {
        float4 v = ((const float4*)src)[i];
        v.x = rnd_tf32(v.x); v.y = rnd_tf32(v.y);
        v.z = rnd_tf32(v.z); v.w = rnd_tf32(v.w);
        *(float4*)(g_w + dstOff + (size_t)i * 4) = v;
    }
}

// ---------------------------------------------------------------------------
// Reduce per-tile partial sums -> row sums.  rows = BB*HH*SS = 65536
// ---------------------------------------------------------------------------
__global__ __launch_bounds__(256)
void reduce_psum_kernel()
{
    int r = blockIdx.x * 256 + threadIdx.x;
    int qr = r & (SS - 1);
    int nt = (qr >> 7) + 1;
    float s = 0.f;
    for (int t = 0; t < nt; t++) s += g_psum[(size_t)r * 8 + t];
    g_rsum[r] = s;
}

// ---------------------------------------------------------------------------
// att_weights[b,q,c] = (1/H) * sum_h probs[b,h,q,c] / rsum[b,h,q]
// ---------------------------------------------------------------------------
__global__ __launch_bounds__(256)
void mean_heads_kernel(float* __restrict__ out)
{
    int b = blockIdx.x >> 10;
    int q = blockIdx.x & (SS - 1);
    int t = threadIdx.x;

    __shared__ float inv[HH];
    if (t < HH) inv[t] = 1.f / g_rsum[((size_t)(b * HH + t)) * SS + q];
    __syncthreads();

    int KC4 = (q >> 2) + 1;
    float4 acc = {0.f, 0.f, 0.f, 0.f};
    if (t < KC4) {
#pragma unroll
        for (int h = 0; h < HH; h++) {
            const float* p = g_probs + (((size_t)(b * HH + h)) * SS + q) * SS + t * 4;
            float4 v = *(const float4*)p;
            float iv = inv[h];
            acc.x += v.x * iv; acc.y += v.y * iv;
            acc.z += v.z * iv; acc.w += v.w * iv;
        }
        const float ih = 1.f / HH;
        acc.x *= ih; acc.y *= ih; acc.z *= ih; acc.w *= ih;
    }
    *(float4*)(out + ((size_t)(b * SS + q)) * SS + t * 4) = acc;
}

// ---------------------------------------------------------------------------
// LayerNorm: one block per row of 1024; output rounded to tf32 (GEMM input).
// ---------------------------------------------------------------------------
__global__ __launch_bounds__(256)
void ln_kernel(const float* __restrict__ xx, int xid,
               const float* __restrict__ g, const float* __restrict__ bt,
               int outid)
{
    const float* x = resolve_c(xx, xid, 0);
    float* out = scratch_ptr(outid);
    int row = blockIdx.x;
    const float* xr = x + (size_t)row * EE;
    int t = threadIdx.x;
    float4 v = *(const float4*)(xr + t * 4);
    float s  = v.x + v.y + v.z + v.w;
    float sq = v.x * v.x + v.y * v.y + v.z * v.z + v.w * v.w;
#pragma unroll
    for (int o = 16; o; o >>= 1) {
        s  += __shfl_xor_sync(0xffffffffu, s, o);
        sq += __shfl_xor_sync(0xffffffffu, sq, o);
    }
    __shared__ float ss[8], sqs[8];
    __shared__ float mu_s, rs_s;
    int w = t >> 5;
    if ((t & 31) == 0) { ss[w] = s; sqs[w] = sq; }
    __syncthreads();
    if (t == 0) {
        float S1 = 0.f, S2 = 0.f;
        for (int i = 0; i < 8; i++) { S1 += ss[i]; S2 += sqs[i]; }
        float mu  = S1 * (1.f / EE);
        float var = S2 * (1.f / EE) - mu * mu;
        mu_s = mu;
        rs_s = rsqrtf(var + 1e-5f);
    }
    __syncthreads();
    float mu = mu_s, rs = rs_s;
    float4 g4 = *(const float4*)(g + t * 4);
    float4 b4 = *(const float4*)(bt + t * 4);
    float4 o;
    o.x = rnd_tf32((v.x - mu) * rs * g4.x + b4.x);
    o.y = rnd_tf32((v.y - mu) * rs * g4.y + b4.y);
    o.z = rnd_tf32((v.z - mu) * rs * g4.z + b4.z);
    o.w = rnd_tf32((v.w - mu) * rs * g4.w + b4.w);
    *(float4*)(out + (size_t)row * EE + t * 4) = o;
}

// ---------------------------------------------------------------------------
// kernel_launch
// Inputs: x, causal_mask, ln1_g, ln1_b, ln2_g, ln2_b,
//   w_in, b_in, w_out, b_out, w_fc, b_fc, w_proj, b_proj
// Output: [x (4096*1024 f32)] then [att_weights (4*1024*1024 f32)]
// ---------------------------------------------------------------------------
extern "C" void kernel_launch(void* const* d_in, const int* in_sizes, int n_in,
                              void* d_out, int out_size)
{
    const float* x     = (const float*)d_in[0];
    const float* ln1g  = (const float*)d_in[2];
    const float* ln1b  = (const float*)d_in[3];
    const float* ln2g  = (const float*)d_in[4];
    const float* ln2b  = (const float*)d_in[5];
    const float* w_in  = (const float*)d_in[6];
    const float* b_in  = (const float*)d_in[7];
    const float* w_out = (const float*)d_in[8];
    const float* b_out = (const float*)d_in[9];
    const float* w_fc  = (const float*)d_in[10];
    const float* b_fc  = (const float*)d_in[11];
    const float* w_proj= (const float*)d_in[12];
    const float* b_proj= (const float*)d_in[13];

    float* outx = (float*)d_out;
    float* outw = outx + (size_t)NTOK * EE;

    const float scale = 0.125f; // 1/sqrt(64)

    // Scratch ids: 0=g_h 1=g_qkv 2=g_probs 3=g_att 4=g_x1 5=g_h2 6=g_fc 7=g_w

    // 0) round weights to tf32 scratch
    round_w_kernel<<<(3 * EE * EE / 4 + 255) / 256, 256>>>(w_in,   WOFF_IN,   3 * EE * EE / 4);
    round_w_kernel<<<(EE * EE / 4 + 255) / 256, 256>>>(w_out,      WOFF_OUT,  EE * EE / 4);
    round_w_kernel<<<(4 * EE * EE / 4 + 255) / 256, 256>>>(w_fc,   WOFF_FC,   4 * EE * EE / 4);
    round_w_kernel<<<(4 * EE * EE / 4 + 255) / 256, 256>>>(w_proj, WOFF_PROJ, 4 * EE * EE / 4);

    // 1) h = LN1(x)  (tf32-rounded output)
    ln_kernel<<<NTOK, 256>>>(x, -1, ln1g, ln1b, 0);

    // 2) qkv = rnd(h @ w_in^T + b_in)    [4096 x 3072]
    mma_gemm<128, 128, 2, 4, EPI_BIAS, true, false>
        <<<dim3(3 * EE / 128, NTOK / 128, 1), 256>>>(
        nullptr, 0, 0,  nullptr, 7, WOFF_IN,  nullptr, 1,
        EE, EE, EE, 3 * EE, b_in, nullptr, -1, 0,
        0, 0, 0, 0, 0, 0, 1, 0.f);

    // 3) probs = rnd(exp(scale * q k^T)) masked + partial row sums  (batched b,h)
    mma_gemm<128, 128, 2, 4, EPI_EXP, true, false>
        <<<dim3(SS / 128, SS / 128, BB * HH), 256>>>(
        nullptr, 1, 0,  nullptr, 1, EE,  nullptr, 2,
        DH, 3 * EE, 3 * EE, SS, nullptr, nullptr, -1, 0,
        (long)SS * 3 * EE, DH, (long)SS * 3 * EE, DH,
        (long)HH * SS * SS, (long)SS * SS, HH, scale);

    // 4) row sums
    reduce_psum_kernel<<<BB * HH * SS / 256, 256>>>();

    // 5) att_weights = mean over heads of normalized probs
    mean_heads_kernel<<<BB * SS, 256>>>(outw);

    // 6) att = rnd((probs @ v) / rsum)   (batched b,h; triangular K)
    mma_gemm<128, 64, 4, 2, EPI_PV, false, true>
        <<<dim3(1, SS / 128, BB * HH), 256>>>(
        nullptr, 2, 0,  nullptr, 1, 2 * EE,  nullptr, 3,
        SS, SS, 3 * EE, EE, nullptr, nullptr, -1, 0,
        (long)HH * SS * SS, (long)SS * SS, (long)SS * 3 * EE, DH,
        (long)SS * EE, DH, HH, 0.f);

    // 7) x1 = x + att @ w_out^T + b_out   (full fp32 output)
    mma_gemm<128, 128, 2, 4, EPI_BIAS_RES, true, false>
        <<<dim3(EE / 128, NTOK / 128, 1), 256>>>(
        nullptr, 3, 0,  nullptr, 7, WOFF_OUT,  nullptr, 4,
        EE, EE, EE, EE, b_out, x, -1, EE,
        0, 0, 0, 0, 0, 0, 1, 0.f);

    // 8) h2 = LN2(x1)  (tf32-rounded output)
    ln_kernel<<<NTOK, 256>>>(nullptr, 4, ln2g, ln2b, 5);

    // 9) fc = rnd(gelu(h2 @ w_fc^T + b_fc))   [4096 x 4096]
    mma_gemm<128, 128, 2, 4, EPI_GELU, true, false>
        <<<dim3(4 * EE / 128, NTOK / 128, 1), 256>>>(
        nullptr, 5, 0,  nullptr, 7, WOFF_FC,  nullptr, 6,
        EE, EE, EE, 4 * EE, b_fc, nullptr, -1, 0,
        0, 0, 0, 0, 0, 0, 1, 0.f);

    // 10) out_x = x1 + fc @ w_proj^T + b_proj   (full fp32 output)
    mma_gemm<128, 128, 2, 4, EPI_BIAS_RES, true, false>
        <<<dim3(EE / 128, NTOK / 128, 1), 256>>>(
        nullptr, 6, 0,  nullptr, 7, WOFF_PROJ,  outx, -1,
        4 * EE, 4 * EE, 4 * EE, EE, b_proj, nullptr, 4, EE,
        0, 0, 0, 0, 0, 0, 1, 0.f);
}

// round 10
// speedup vs baseline: 1.8329x; 1.8329x over previous
#include <cuda_runtime.h>
#include <cuda_fp16.h>
#include <math.h>
#include <stdint.h>

// ---------------------------------------------------------------------------
// Problem constants: B=4, S=1024, E=1024, H=16, DH=64
// ---------------------------------------------------------------------------
#define BB   4
#define SS   1024
#define EE   1024
#define HH   16
#define DH   64
#define NTOK (BB * SS)          // 4096 rows

// ---------------------------------------------------------------------------
// Scratch (static device globals; no allocation allowed anywhere)
// ---------------------------------------------------------------------------
__device__ __half g_h    [(size_t)NTOK * EE];
__device__ __half g_qkv  [(size_t)NTOK * 3 * EE];
__device__ __half g_probs[(size_t)BB * HH * SS * SS];   // unnormalized exp scores (half)
__device__ __half g_att  [(size_t)NTOK * EE];
__device__ float  g_x1   [(size_t)NTOK * EE];           // residual chain stays fp32
__device__ __half g_h2   [(size_t)NTOK * EE];
__device__ __half g_fc   [(size_t)NTOK * 4 * EE];
__device__ __half g_w    [(size_t)12 * 1024 * 1024];    // half weights
__device__ float  g_psum [(size_t)BB * HH * SS * 8];
__device__ float  g_rsum [(size_t)BB * HH * SS];

// g_w offsets (elements)
#define WOFF_IN   0L
#define WOFF_OUT  (3L * 1024 * 1024)
#define WOFF_FC   (4L * 1024 * 1024)
#define WOFF_PROJ (8L * 1024 * 1024)

__device__ __forceinline__ void* scratch_ptr(int id) {
    switch (id) {
        case 0:  return (void*)g_h;
        case 1:  return (void*)g_qkv;
        case 2:  return (void*)g_probs;
        case 3:  return (void*)g_att;
        case 4:  return (void*)g_x1;
        case 5:  return (void*)g_h2;
        case 7:  return (void*)g_w;
        default: return (void*)g_fc;
    }
}
__device__ __forceinline__ const __half* resolve_h(int id, long off) {
    return (const __half*)scratch_ptr(id) + off;
}
__device__ __forceinline__ const float* resolve_f(const float* ext, int id) {
    return id >= 0 ? (const float*)scratch_ptr(id) : ext;
}

__device__ __forceinline__ float gelu_f(float v) {
    const float c = 0.7978845608028654f;
    float t = tanhf(c * (v + 0.044715f * v * v * v));
    return 0.5f * v * (1.f + t);
}

// fp16 tensor-core mma: m16n8k16, fp32 accumulate
__device__ __forceinline__ void mma_f16(float* c, const uint32_t* a, const uint32_t* b) {
    asm volatile(
        "mma.sync.aligned.m16n8k16.row.col.f32.f16.f16.f32 "
        "{%0,%1,%2,%3}, {%4,%5,%6,%7}, {%8,%9}, {%0,%1,%2,%3};"
        : "+f"(c[0]), "+f"(c[1]), "+f"(c[2]), "+f"(c[3])
        : "r"(a[0]), "r"(a[1]), "r"(a[2]), "r"(a[3]), "r"(b[0]), "r"(b[1]));
}

__device__ __forceinline__ void cp16(void* dst, const void* src) {
    uint32_t d = (uint32_t)__cvta_generic_to_shared(dst);
    asm volatile("cp.async.ca.shared.global [%0], [%1], 16;\n" :: "r"(d), "l"(src));
}
__device__ __forceinline__ void cp_commit() {
    asm volatile("cp.async.commit_group;\n");
}
template <int N>
__device__ __forceinline__ void cp_wait() {
    asm volatile("cp.async.wait_group %0;\n" :: "n"(N));
}

enum { EPI_BIAS = 1, EPI_BIAS_RES = 2, EPI_GELU = 3, EPI_EXP = 4, EPI_PV = 5 };

// ---------------------------------------------------------------------------
// fp16 tensor-core GEMM, cp.async double buffered, fp32 accumulate.
//   A, B stored as __half in device scratch.
//   B_NT=true : B stored [N,K] row-major (C = A * B^T)
//   B_NT=false: B stored [K,N] row-major (C = A * B)
// Block tile BM x BN x 32(halves), 256 threads = WARPS_M x WARPS_N warps,
// m16n8k16 fragments.
// EPI_EXP: p = half(exp(scale*s)) masked causal + per-tile partial row sums
//          (sums of the half-rounded values); fully-masked tiles exit.
// EPI_PV : divide by g_rsum[row]; TRI_K truncates K at bm+BM.
// C dtype: fp32 for EPI_BIAS_RES, half otherwise.
// ---------------------------------------------------------------------------
template <int BM, int BN, int WARPS_M, int WARPS_N, int EPI, bool B_NT, bool TRI_K>
__global__ __launch_bounds__(256)
void mma_gemm(int Aid, long Aoff, int Bid, long Boff,
              void* __restrict__ Cx, int Cid,
              int K, int lda, int ldb, int ldc,
              const float* __restrict__ bias,
              const float* __restrict__ Rx, int Rid, int ldres,
              long aOuter, long aInner, long bOuter, long bInner,
              long cOuter, long cInner, int Hdim, float scale)
{
    constexpr int BK  = 32;                 // halves per K tile
    constexpr int AKP = BK + 8;             // 40-half rows: conflict-free frag LDS
    constexpr int WM = BM / WARPS_M, WN = BN / WARPS_N;
    constexpr int MF = WM / 16, NF = WN / 8;
    constexpr int BD1 = B_NT ? BN : BK;
    constexpr int BD2 = B_NT ? AKP : (BN + 8);
    constexpr int RP1 = (EPI == EPI_EXP) ? WARPS_N : 1;
    constexpr int RP2 = (EPI == EPI_EXP) ? BM : 1;
    constexpr bool C_F32 = (EPI == EPI_BIAS_RES);

    int bm = blockIdx.y * BM, bn = blockIdx.x * BN;
    if (EPI == EPI_EXP && bn >= bm + BM) return;

    const __half* A = resolve_h(Aid, Aoff);
    const __half* B = resolve_h(Bid, Boff);
    char* Cc = (Cid >= 0) ? (char*)scratch_ptr(Cid) : (char*)Cx;

    int z  = blockIdx.z;
    int zo = z / Hdim, zi = z - zo * Hdim;
    A += (size_t)zo * aOuter + (size_t)zi * aInner;
    B += (size_t)zo * bOuter + (size_t)zi * bInner;
    size_t cBase = (size_t)zo * cOuter + (size_t)zi * cInner;

    __shared__ __align__(16) __half As[2][BM][AKP];
    __shared__ __align__(16) __half Bs[2][BD1][BD2];
    __shared__ float rowp[RP1][RP2];

    int tid  = threadIdx.x;
    int wid  = tid >> 5, lane = tid & 31;
    int g    = lane >> 2, tig = lane & 3;
    int wm   = (wid / WARPS_N) * WM;
    int wn   = (wid % WARPS_N) * WN;
    int wnIdx = wid % WARPS_N;

    const __half* Ag = A + (size_t)bm * lda;
    const __half* Bg = B_NT ? (B + (size_t)bn * ldb) : B;

    int Kend = TRI_K ? min(K, bm + BM) : K;
    int T = Kend / BK;

    float acc[MF][NF][4] = {};

    // A tile: BM rows x 32 halves (4x 16B chunks per row)
    auto loadA = [&](int st, int k0) {
#pragma unroll
        for (int i = 0; i < BM / 64; i++) {
            int c = tid + i * 256;
            int m = c >> 2, q = c & 3;
            cp16(&As[st][m][q * 8], Ag + (size_t)m * lda + k0 + q * 8);
        }
    };
    auto loadB = [&](int st, int k0) {
        if (B_NT) {
#pragma unroll
            for (int i = 0; i < BN / 64; i++) {
                int c = tid + i * 256;
                int n = c >> 2, q = c & 3;
                cp16(&Bs[st][n][q * 8], Bg + (size_t)n * ldb + k0 + q * 8);
            }
        } else {
            constexpr int CPR = BN / 8;     // 16B chunks per row
#pragma unroll
            for (int i = 0; i < (BK * CPR + 255) / 256; i++) {
                int c = tid + i * 256;
                if (BK * CPR % 256 == 0 || c < BK * CPR) {
                    int k = c / CPR, n8 = c % CPR;
                    cp16(&Bs[st][k][n8 * 8], B + (size_t)(k0 + k) * ldb + bn + n8 * 8);
                }
            }
        }
    };

    loadA(0, 0); loadB(0, 0); cp_commit();

    int buf = 0;
    for (int it = 0; it < T; it++) {
        if (it + 1 < T) {
            loadA(buf ^ 1, (it + 1) * BK);
            loadB(buf ^ 1, (it + 1) * BK);
            cp_commit();
            cp_wait<1>();
        } else {
            cp_wait<0>();
        }
        __syncthreads();

#pragma unroll
        for (int kk = 0; kk < BK; kk += 16) {
            uint32_t af[MF][4], bf[NF][2];
#pragma unroll
            for (int mf = 0; mf < MF; mf++) {
                int mb = wm + mf * 16 + g;
                af[mf][0] = *(const uint32_t*)&As[buf][mb    ][kk + tig * 2    ];
                af[mf][1] = *(const uint32_t*)&As[buf][mb + 8][kk + tig * 2    ];
                af[mf][2] = *(const uint32_t*)&As[buf][mb    ][kk + tig * 2 + 8];
                af[mf][3] = *(const uint32_t*)&As[buf][mb + 8][kk + tig * 2 + 8];
            }
#pragma unroll
            for (int nf = 0; nf < NF; nf++) {
                int nb = wn + nf * 8 + g;
                if (B_NT) {
                    bf[nf][0] = *(const uint32_t*)&Bs[buf][nb][kk + tig * 2    ];
                    bf[nf][1] = *(const uint32_t*)&Bs[buf][nb][kk + tig * 2 + 8];
                } else {
                    uint32_t l0 = __half_as_ushort(Bs[buf][kk + tig * 2    ][nb]);
                    uint32_t h0 = __half_as_ushort(Bs[buf][kk + tig * 2 + 1][nb]);
                    uint32_t l1 = __half_as_ushort(Bs[buf][kk + tig * 2 + 8][nb]);
                    uint32_t h1 = __half_as_ushort(Bs[buf][kk + tig * 2 + 9][nb]);
                    bf[nf][0] = l0 | (h0 << 16);
                    bf[nf][1] = l1 | (h1 << 16);
                }
            }
#pragma unroll
            for (int mf = 0; mf < MF; mf++)
#pragma unroll
                for (int nf = 0; nf < NF; nf++)
                    mma_f16(acc[mf][nf], af[mf], bf[nf]);
        }
        __syncthreads();
        buf ^= 1;
    }

    // ---- epilogue ----
    const float* R = (EPI == EPI_BIAS_RES) ? resolve_f(Rx, Rid) : nullptr;

    float s0[MF], s1[MF];
    if (EPI == EPI_EXP) {
#pragma unroll
        for (int mf = 0; mf < MF; mf++) { s0[mf] = 0.f; s1[mf] = 0.f; }
    }

#pragma unroll
    for (int mf = 0; mf < MF; mf++) {
#pragma unroll
        for (int nf = 0; nf < NF; nf++) {
            int r0 = bm + wm + mf * 16 + g;
            int r1 = r0 + 8;
            int c  = bn + wn + nf * 8 + tig * 2;
            float v0 = acc[mf][nf][0], v1 = acc[mf][nf][1];
            float v2 = acc[mf][nf][2], v3 = acc[mf][nf][3];
            if (EPI == EPI_BIAS || EPI == EPI_BIAS_RES || EPI == EPI_GELU) {
                float b0 = bias[c], b1 = bias[c + 1];
                v0 += b0; v1 += b1; v2 += b0; v3 += b1;
            }
            if (EPI == EPI_BIAS_RES) {
                float2 ra = *(const float2*)(R + (size_t)r0 * ldres + c);
                float2 rb = *(const float2*)(R + (size_t)r1 * ldres + c);
                v0 += ra.x; v1 += ra.y; v2 += rb.x; v3 += rb.y;
            }
            if (EPI == EPI_GELU) {
                v0 = gelu_f(v0); v1 = gelu_f(v1);
                v2 = gelu_f(v2); v3 = gelu_f(v3);
            }
            if (EPI == EPI_EXP) {
                v0 = (c     <= r0) ? __expf(v0 * scale) : 0.f;
                v1 = (c + 1 <= r0) ? __expf(v1 * scale) : 0.f;
                v2 = (c     <= r1) ? __expf(v2 * scale) : 0.f;
                v3 = (c + 1 <= r1) ? __expf(v3 * scale) : 0.f;
            }
            if (EPI == EPI_PV) {
                float i0 = 1.f / g_rsum[(size_t)z * SS + r0];
                float i1 = 1.f / g_rsum[(size_t)z * SS + r1];
                v0 *= i0; v1 *= i0; v2 *= i1; v3 *= i1;
            }
            if (C_F32) {
                float* Cf = (float*)Cc + cBase;
                float2 oa = {v0, v1}, ob = {v2, v3};
                *(float2*)(Cf + (size_t)r0 * ldc + c) = oa;
                *(float2*)(Cf + (size_t)r1 * ldc + c) = ob;
            } else {
                __half* Ch = (__half*)Cc + cBase;
                __half2 ha = __floats2half2_rn(v0, v1);
                __half2 hb = __floats2half2_rn(v2, v3);
                *(__half2*)(Ch + (size_t)r0 * ldc + c) = ha;
                *(__half2*)(Ch + (size_t)r1 * ldc + c) = hb;
                if (EPI == EPI_EXP) {
                    float2 fa = __half22float2(ha);
                    float2 fb = __half22float2(hb);
                    s0[mf] += fa.x + fa.y;
                    s1[mf] += fb.x + fb.y;
                }
            }
        }
    }

    if (EPI == EPI_EXP) {
#pragma unroll
        for (int mf = 0; mf < MF; mf++) {
            s0[mf] += __shfl_xor_sync(0xffffffffu, s0[mf], 1);
            s0[mf] += __shfl_xor_sync(0xffffffffu, s0[mf], 2);
            s1[mf] += __shfl_xor_sync(0xffffffffu, s1[mf], 1);
            s1[mf] += __shfl_xor_sync(0xffffffffu, s1[mf], 2);
            if (tig == 0) {
                rowp[wnIdx][wm + mf * 16 + g    ] = s0[mf];
                rowp[wnIdx][wm + mf * 16 + g + 8] = s1[mf];
            }
        }
        __syncthreads();
        if (tid < BM) {
            float t = 0.f;
#pragma unroll
            for (int w = 0; w < WARPS_N; w++) t += rowp[w][tid];
            g_psum[((size_t)z * SS + bm + tid) * 8 + blockIdx.x] = t;
        }
    }
}

// ---------------------------------------------------------------------------
// Convert fp32 weights to half into g_w.
// ---------------------------------------------------------------------------
__global__ __launch_bounds__(256)
void cvt_w_kernel(const float* __restrict__ src, long dstOff, int n4)
{
    int i = blockIdx.x * 256 + threadIdx.x;
    if (i < n4) {
        float4 v = ((const float4*)src)[i];
        __half2 a = __floats2half2_rn(v.x, v.y);
        __half2 b = __floats2half2_rn(v.z, v.w);
        *(__half2*)(g_w + dstOff + (size_t)i * 4)     = a;
        *(__half2*)(g_w + dstOff + (size_t)i * 4 + 2) = b;
    }
}

// ---------------------------------------------------------------------------
// Reduce per-tile partial sums -> row sums.
// ---------------------------------------------------------------------------
__global__ __launch_bounds__(256)
void reduce_psum_kernel()
{
    int r = blockIdx.x * 256 + threadIdx.x;
    int qr = r & (SS - 1);
    int nt = (qr >> 7) + 1;
    float s = 0.f;
    for (int t = 0; t < nt; t++) s += g_psum[(size_t)r * 8 + t];
    g_rsum[r] = s;
}

// ---------------------------------------------------------------------------
// att_weights[b,q,c] = (1/H) * sum_h probs[b,h,q,c] / rsum[b,h,q]
// probs are half; reads only cols <= q.
// ---------------------------------------------------------------------------
__global__ __launch_bounds__(256)
void mean_heads_kernel(float* __restrict__ out)
{
    int b = blockIdx.x >> 10;
    int q = blockIdx.x & (SS - 1);
    int t = threadIdx.x;

    __shared__ float inv[HH];
    if (t < HH) inv[t] = 1.f / g_rsum[((size_t)(b * HH + t)) * SS + q];
    __syncthreads();

    int KC4 = (q >> 2) + 1;
    float4 acc = {0.f, 0.f, 0.f, 0.f};
    if (t < KC4) {
#pragma unroll
        for (int h = 0; h < HH; h++) {
            const __half* p = g_probs + (((size_t)(b * HH + h)) * SS + q) * SS + t * 4;
            __half2 pa = *(const __half2*)p;
            __half2 pb = *(const __half2*)(p + 2);
            float2 fa = __half22float2(pa);
            float2 fb = __half22float2(pb);
            float iv = inv[h];
            acc.x += fa.x * iv; acc.y += fa.y * iv;
            acc.z += fb.x * iv; acc.w += fb.y * iv;
        }
        const float ih = 1.f / HH;
        acc.x *= ih; acc.y *= ih; acc.z *= ih; acc.w *= ih;
    }
    *(float4*)(out + ((size_t)(b * SS + q)) * SS + t * 4) = acc;
}

// ---------------------------------------------------------------------------
// LayerNorm: fp32 in (external x or g_x1), half out (GEMM operand).
// ---------------------------------------------------------------------------
__global__ __launch_bounds__(256)
void ln_kernel(const float* __restrict__ xx, int xid,
               const float* __restrict__ g, const float* __restrict__ bt,
               int outid)
{
    const float* x = resolve_f(xx, xid);
    __half* out = (__half*)scratch_ptr(outid);
    int row = blockIdx.x;
    const float* xr = x + (size_t)row * EE;
    int t = threadIdx.x;
    float4 v = *(const float4*)(xr + t * 4);
    float s  = v.x + v.y + v.z + v.w;
    float sq = v.x * v.x + v.y * v.y + v.z * v.z + v.w * v.w;
#pragma unroll
    for (int o = 16; o; o >>= 1) {
        s  += __shfl_xor_sync(0xffffffffu, s, o);
        sq += __shfl_xor_sync(0xffffffffu, sq, o);
    }
    __shared__ float ss[8], sqs[8];
    __shared__ float mu_s, rs_s;
    int w = t >> 5;
    if ((t & 31) == 0) { ss[w] = s; sqs[w] = sq; }
    __syncthreads();
    if (t == 0) {
        float S1 = 0.f, S2 = 0.f;
        for (int i = 0; i < 8; i++) { S1 += ss[i]; S2 += sqs[i]; }
        float mu  = S1 * (1.f / EE);
        float var = S2 * (1.f / EE) - mu * mu;
        mu_s = mu;
        rs_s = rsqrtf(var + 1e-5f);
    }
    __syncthreads();
    float mu = mu_s, rs = rs_s;
    float4 g4 = *(const float4*)(g + t * 4);
    float4 b4 = *(const float4*)(bt + t * 4);
    __half2 oa = __floats2half2_rn((v.x - mu) * rs * g4.x + b4.x,
                                   (v.y - mu) * rs * g4.y + b4.y);
    __half2 ob = __floats2half2_rn((v.z - mu) * rs * g4.z + b4.z,
                                   (v.w - mu) * rs * g4.w + b4.w);
    *(__half2*)(out + (size_t)row * EE + t * 4)     = oa;
    *(__half2*)(out + (size_t)row * EE + t * 4 + 2) = ob;
}

// ---------------------------------------------------------------------------
// kernel_launch
// Inputs: x, causal_mask, ln1_g, ln1_b, ln2_g, ln2_b,
//   w_in, b_in, w_out, b_out, w_fc, b_fc, w_proj, b_proj
// Output: [x (4096*1024 f32)] then [att_weights (4*1024*1024 f32)]
// ---------------------------------------------------------------------------
extern "C" void kernel_launch(void* const* d_in, const int* in_sizes, int n_in,
                              void* d_out, int out_size)
{
    const float* x     = (const float*)d_in[0];
    const float* ln1g  = (const float*)d_in[2];
    const float* ln1b  = (const float*)d_in[3];
    const float* ln2g  = (const float*)d_in[4];
    const float* ln2b  = (const float*)d_in[5];
    const float* w_in  = (const float*)d_in[6];
    const float* b_in  = (const float*)d_in[7];
    const float* w_out = (const float*)d_in[8];
    const float* b_out = (const float*)d_in[9];
    const float* w_fc  = (const float*)d_in[10];
    const float* b_fc  = (const float*)d_in[11];
    const float* w_proj= (const float*)d_in[12];
    const float* b_proj= (const float*)d_in[13];

    float* outx = (float*)d_out;
    float* outw = outx + (size_t)NTOK * EE;

    const float scale = 0.125f; // 1/sqrt(64)

    // Scratch ids: 0=g_h 1=g_qkv 2=g_probs 3=g_att 4=g_x1 5=g_h2 6=g_fc 7=g_w

    // 0) convert weights to half
    cvt_w_kernel<<<3 * EE * EE / 4 / 256, 256>>>(w_in,   WOFF_IN,   3 * EE * EE / 4);
    cvt_w_kernel<<<EE * EE / 4 / 256, 256>>>(w_out,      WOFF_OUT,  EE * EE / 4);
    cvt_w_kernel<<<4 * EE * EE / 4 / 256, 256>>>(w_fc,   WOFF_FC,   4 * EE * EE / 4);
    cvt_w_kernel<<<4 * EE * EE / 4 / 256, 256>>>(w_proj, WOFF_PROJ, 4 * EE * EE / 4);

    // 1) h = LN1(x)  (half out)
    ln_kernel<<<NTOK, 256>>>(x, -1, ln1g, ln1b, 0);

    // 2) qkv = half(h @ w_in^T + b_in)    [4096 x 3072]
    mma_gemm<128, 128, 2, 4, EPI_BIAS, true, false>
        <<<dim3(3 * EE / 128, NTOK / 128, 1), 256>>>(
        0, 0,  7, WOFF_IN,  nullptr, 1,
        EE, EE, EE, 3 * EE, b_in, nullptr, -1, 0,
        0, 0, 0, 0, 0, 0, 1, 0.f);

    // 3) probs = half(exp(scale * q k^T)) masked + partial row sums (batched b,h)
    mma_gemm<128, 128, 2, 4, EPI_EXP, true, false>
        <<<dim3(SS / 128, SS / 128, BB * HH), 256>>>(
        1, 0,  1, EE,  nullptr, 2,
        DH, 3 * EE, 3 * EE, SS, nullptr, nullptr, -1, 0,
        (long)SS * 3 * EE, DH, (long)SS * 3 * EE, DH,
        (long)HH * SS * SS, (long)SS * SS, HH, scale);

    // 4) row sums
    reduce_psum_kernel<<<BB * HH * SS / 256, 256>>>();

    // 5) att_weights = mean over heads of normalized probs
    mean_heads_kernel<<<BB * SS, 256>>>(outw);

    // 6) att = half((probs @ v) / rsum)   (batched b,h; triangular K)
    mma_gemm<128, 64, 4, 2, EPI_PV, false, true>
        <<<dim3(1, SS / 128, BB * HH), 256>>>(
        2, 0,  1, 2 * EE,  nullptr, 3,
        SS, SS, 3 * EE, EE, nullptr, nullptr, -1, 0,
        (long)HH * SS * SS, (long)SS * SS, (long)SS * 3 * EE, DH,
        (long)SS * EE, DH, HH, 0.f);

    // 7) x1 = x + att @ w_out^T + b_out   (fp32 out)
    mma_gemm<128, 128, 2, 4, EPI_BIAS_RES, true, false>
        <<<dim3(EE / 128, NTOK / 128, 1), 256>>>(
        3, 0,  7, WOFF_OUT,  nullptr, 4,
        EE, EE, EE, EE, b_out, x, -1, EE,
        0, 0, 0, 0, 0, 0, 1, 0.f);

    // 8) h2 = LN2(x1)  (half out)
    ln_kernel<<<NTOK, 256>>>(nullptr, 4, ln2g, ln2b, 5);

    // 9) fc = half(gelu(h2 @ w_fc^T + b_fc))   [4096 x 4096]
    mma_gemm<128, 128, 2, 4, EPI_GELU, true, false>
        <<<dim3(4 * EE / 128, NTOK / 128, 1), 256>>>(
        5, 0,  7, WOFF_FC,  nullptr, 6,
        EE, EE, EE, 4 * EE, b_fc, nullptr, -1, 0,
        0, 0, 0, 0, 0, 0, 1, 0.f);

    // 10) out_x = x1 + fc @ w_proj^T + b_proj   (fp32 out)
    mma_gemm<128, 128, 2, 4, EPI_BIAS_RES, true, false>
        <<<dim3(EE / 128, NTOK / 128, 1), 256>>>(
        6, 0,  7, WOFF_PROJ,  outx, -1,
        4 * EE, 4 * EE, 4 * EE, EE, b_proj, nullptr, 4, EE,
        0, 0, 0, 0, 0, 0, 1, 0.f);
}

// round 11
// speedup vs baseline: 1.9663x; 1.0728x over previous
#include <cuda_runtime.h>
#include <cuda_fp16.h>
#include <math.h>
#include <stdint.h>

// ---------------------------------------------------------------------------
// Problem constants: B=4, S=1024, E=1024, H=16, DH=64
// ---------------------------------------------------------------------------
#define BB   4
#define SS   1024
#define EE   1024
#define HH   16
#define DH   64
#define NTOK (BB * SS)          // 4096 rows

// ---------------------------------------------------------------------------
// Scratch (static device globals; no allocation allowed anywhere)
// ---------------------------------------------------------------------------
__device__ __half g_h    [(size_t)NTOK * EE];
__device__ __half g_qkv  [(size_t)NTOK * 3 * EE];
__device__ __half g_probs[(size_t)BB * HH * SS * SS];   // unnormalized exp scores (half)
__device__ __half g_att  [(size_t)NTOK * EE];
__device__ float  g_x1   [(size_t)NTOK * EE];           // residual chain stays fp32
__device__ __half g_h2   [(size_t)NTOK * EE];
__device__ __half g_fc   [(size_t)NTOK * 4 * EE];
__device__ __half g_w    [(size_t)12 * 1024 * 1024];    // half weights
__device__ float  g_psum [(size_t)BB * HH * SS * 8];
__device__ float  g_rsum [(size_t)BB * HH * SS];

// g_w offsets (elements)
#define WOFF_IN   0L
#define WOFF_OUT  (3L * 1024 * 1024)
#define WOFF_FC   (4L * 1024 * 1024)
#define WOFF_PROJ (8L * 1024 * 1024)

__device__ __forceinline__ void* scratch_ptr(int id) {
    switch (id) {
        case 0:  return (void*)g_h;
        case 1:  return (void*)g_qkv;
        case 2:  return (void*)g_probs;
        case 3:  return (void*)g_att;
        case 4:  return (void*)g_x1;
        case 5:  return (void*)g_h2;
        case 7:  return (void*)g_w;
        default: return (void*)g_fc;
    }
}
__device__ __forceinline__ const __half* resolve_h(int id, long off) {
    return (const __half*)scratch_ptr(id) + off;
}
__device__ __forceinline__ const float* resolve_f(const float* ext, int id) {
    return id >= 0 ? (const float*)scratch_ptr(id) : ext;
}

__device__ __forceinline__ float gelu_f(float v) {
    const float c = 0.7978845608028654f;
    float t = tanhf(c * (v + 0.044715f * v * v * v));
    return 0.5f * v * (1.f + t);
}

// fp16 tensor-core mma: m16n8k16, fp32 accumulate
__device__ __forceinline__ void mma_f16(float* c, const uint32_t* a, const uint32_t* b) {
    asm volatile(
        "mma.sync.aligned.m16n8k16.row.col.f32.f16.f16.f32 "
        "{%0,%1,%2,%3}, {%4,%5,%6,%7}, {%8,%9}, {%0,%1,%2,%3};"
        : "+f"(c[0]), "+f"(c[1]), "+f"(c[2]), "+f"(c[3])
        : "r"(a[0]), "r"(a[1]), "r"(a[2]), "r"(a[3]), "r"(b[0]), "r"(b[1]));
}

__device__ __forceinline__ void ldsm4(uint32_t* r, uint32_t a) {
    asm volatile("ldmatrix.sync.aligned.m8n8.x4.shared.b16 {%0,%1,%2,%3}, [%4];"
        : "=r"(r[0]), "=r"(r[1]), "=r"(r[2]), "=r"(r[3]) : "r"(a));
}

__device__ __forceinline__ void cp16(void* dst, const void* src) {
    uint32_t d = (uint32_t)__cvta_generic_to_shared(dst);
    asm volatile("cp.async.ca.shared.global [%0], [%1], 16;\n" :: "r"(d), "l"(src));
}
__device__ __forceinline__ void cp_commit() {
    asm volatile("cp.async.commit_group;\n");
}
template <int N>
__device__ __forceinline__ void cp_wait() {
    asm volatile("cp.async.wait_group %0;\n" :: "n"(N));
}

enum { EPI_BIAS = 1, EPI_BIAS_RES = 2, EPI_GELU = 3, EPI_EXP = 4, EPI_PV = 5 };

// ---------------------------------------------------------------------------
// fp16 tensor-core GEMM, cp.async double buffered, fp32 accumulate.
//   A, B stored as __half in device scratch.
//   B_NT=true : B stored [N,K] row-major (C = A * B^T)  — ldmatrix fragments
//   B_NT=false: B stored [K,N] row-major (C = A * B)    — scalar B fragments
// Block tile BM x BN x 32(halves), 256 threads = WARPS_M x WARPS_N warps,
// m16n8k16 fragments, ldmatrix.x4 loads for A (and B when B_NT).
// EPI_EXP: p = half(exp(scale*s)) masked causal + per-tile partial row sums;
//          fully-masked tiles exit. EPI_PV: /rsum, TRI_K.
// ---------------------------------------------------------------------------
template <int BM, int BN, int WARPS_M, int WARPS_N, int EPI, bool B_NT, bool TRI_K>
__global__ __launch_bounds__(256)
void mma_gemm(int Aid, long Aoff, int Bid, long Boff,
              void* __restrict__ Cx, int Cid,
              int K, int lda, int ldb, int ldc,
              const float* __restrict__ bias,
              const float* __restrict__ Rx, int Rid, int ldres,
              long aOuter, long aInner, long bOuter, long bInner,
              long cOuter, long cInner, int Hdim, float scale)
{
    constexpr int BK  = 32;                 // halves per K tile
    constexpr int AKP = BK + 8;             // 40-half rows (80B): conflict-free LDSM
    constexpr int WM = BM / WARPS_M, WN = BN / WARPS_N;
    constexpr int MF = WM / 16, NF = WN / 8;
    constexpr int BD1 = B_NT ? BN : BK;
    constexpr int BD2 = B_NT ? AKP : (BN + 8);
    constexpr int RP1 = (EPI == EPI_EXP) ? WARPS_N : 1;
    constexpr int RP2 = (EPI == EPI_EXP) ? BM : 1;
    constexpr bool C_F32 = (EPI == EPI_BIAS_RES);

    int bm = blockIdx.y * BM, bn = blockIdx.x * BN;
    if (EPI == EPI_EXP && bn >= bm + BM) return;

    const __half* A = resolve_h(Aid, Aoff);
    const __half* B = resolve_h(Bid, Boff);
    char* Cc = (Cid >= 0) ? (char*)scratch_ptr(Cid) : (char*)Cx;

    int z  = blockIdx.z;
    int zo = z / Hdim, zi = z - zo * Hdim;
    A += (size_t)zo * aOuter + (size_t)zi * aInner;
    B += (size_t)zo * bOuter + (size_t)zi * bInner;
    size_t cBase = (size_t)zo * cOuter + (size_t)zi * cInner;

    __shared__ __align__(16) __half As[2][BM][AKP];
    __shared__ __align__(16) __half Bs[2][BD1][BD2];
    __shared__ float rowp[RP1][RP2];

    int tid  = threadIdx.x;
    int wid  = tid >> 5, lane = tid & 31;
    int g    = lane >> 2, tig = lane & 3;
    int wm   = (wid / WARPS_N) * WM;
    int wn   = (wid % WARPS_N) * WN;
    int wnIdx = wid % WARPS_N;

    const __half* Ag = A + (size_t)bm * lda;
    const __half* Bg = B_NT ? (B + (size_t)bn * ldb) : B;

    int Kend = TRI_K ? min(K, bm + BM) : K;
    int T = Kend / BK;

    float acc[MF][NF][4] = {};

    // ---- ldmatrix base addresses (byte, shared space) ----
    uint32_t smA = (uint32_t)__cvta_generic_to_shared(&As[0][0][0]);
    uint32_t smB = (uint32_t)__cvta_generic_to_shared(&Bs[0][0][0]);
    const uint32_t aBuf = (uint32_t)(BM * AKP * 2);
    const uint32_t bBuf = (uint32_t)(BD1 * BD2 * 2);
    // A: lane -> row (lane&15), k-offset (lane>>4)*8
    uint32_t aAddr = smA + (uint32_t)(((wm + (lane & 15)) * AKP + ((lane >> 4) * 8)) * 2);
    // B (B_NT): lane -> n row (lane&7)+(lane>>4)*8, k-offset ((lane>>3)&1)*8
    uint32_t bAddr = smB + (uint32_t)(((wn + (lane & 7) + ((lane >> 4) * 8)) * AKP
                                       + (((lane >> 3) & 1) * 8)) * 2);

    auto loadA = [&](int st, int k0) {
#pragma unroll
        for (int i = 0; i < BM / 64; i++) {
            int c = tid + i * 256;
            int m = c >> 2, q = c & 3;
            cp16(&As[st][m][q * 8], Ag + (size_t)m * lda + k0 + q * 8);
        }
    };
    auto loadB = [&](int st, int k0) {
        if (B_NT) {
#pragma unroll
            for (int i = 0; i < BN / 64; i++) {
                int c = tid + i * 256;
                int n = c >> 2, q = c & 3;
                cp16(&Bs[st][n][q * 8], Bg + (size_t)n * ldb + k0 + q * 8);
            }
        } else {
            constexpr int CPR = BN / 8;
#pragma unroll
            for (int i = 0; i < (BK * CPR + 255) / 256; i++) {
                int c = tid + i * 256;
                if (BK * CPR % 256 == 0 || c < BK * CPR) {
                    int k = c / CPR, n8 = c % CPR;
                    cp16(&Bs[st][k][n8 * 8], B + (size_t)(k0 + k) * ldb + bn + n8 * 8);
                }
            }
        }
    };

    loadA(0, 0); loadB(0, 0); cp_commit();

    int buf = 0;
    for (int it = 0; it < T; it++) {
        if (it + 1 < T) {
            loadA(buf ^ 1, (it + 1) * BK);
            loadB(buf ^ 1, (it + 1) * BK);
            cp_commit();
            cp_wait<1>();
        } else {
            cp_wait<0>();
        }
        __syncthreads();

        uint32_t aB = aAddr + buf * aBuf;
        uint32_t bB = bAddr + buf * bBuf;

#pragma unroll
        for (int kk = 0; kk < BK; kk += 16) {
            uint32_t af[MF][4], bf[NF][2];
#pragma unroll
            for (int mf = 0; mf < MF; mf++)
                ldsm4(af[mf], aB + (uint32_t)((mf * 16 * AKP + kk) * 2));
            if (B_NT) {
#pragma unroll
                for (int nfp = 0; nfp < NF / 2; nfp++) {
                    uint32_t bq[4];
                    ldsm4(bq, bB + (uint32_t)((nfp * 16 * AKP + kk) * 2));
                    bf[nfp * 2    ][0] = bq[0]; bf[nfp * 2    ][1] = bq[1];
                    bf[nfp * 2 + 1][0] = bq[2]; bf[nfp * 2 + 1][1] = bq[3];
                }
            } else {
#pragma unroll
                for (int nf = 0; nf < NF; nf++) {
                    int nb = wn + nf * 8 + g;
                    uint32_t l0 = __half_as_ushort(Bs[buf][kk + tig * 2    ][nb]);
                    uint32_t h0 = __half_as_ushort(Bs[buf][kk + tig * 2 + 1][nb]);
                    uint32_t l1 = __half_as_ushort(Bs[buf][kk + tig * 2 + 8][nb]);
                    uint32_t h1 = __half_as_ushort(Bs[buf][kk + tig * 2 + 9][nb]);
                    bf[nf][0] = l0 | (h0 << 16);
                    bf[nf][1] = l1 | (h1 << 16);
                }
            }
#pragma unroll
            for (int mf = 0; mf < MF; mf++)
#pragma unroll
                for (int nf = 0; nf < NF; nf++)
                    mma_f16(acc[mf][nf], af[mf], bf[nf]);
        }
        __syncthreads();
        buf ^= 1;
    }

    // ---- epilogue ----
    const float* R = (EPI == EPI_BIAS_RES) ? resolve_f(Rx, Rid) : nullptr;

    float s0[MF], s1[MF];
    if (EPI == EPI_EXP) {
#pragma unroll
        for (int mf = 0; mf < MF; mf++) { s0[mf] = 0.f; s1[mf] = 0.f; }
    }

#pragma unroll
    for (int mf = 0; mf < MF; mf++) {
#pragma unroll
        for (int nf = 0; nf < NF; nf++) {
            int r0 = bm + wm + mf * 16 + g;
            int r1 = r0 + 8;
            int c  = bn + wn + nf * 8 + tig * 2;
            float v0 = acc[mf][nf][0], v1 = acc[mf][nf][1];
            float v2 = acc[mf][nf][2], v3 = acc[mf][nf][3];
            if (EPI == EPI_BIAS || EPI == EPI_BIAS_RES || EPI == EPI_GELU) {
                float b0 = bias[c], b1 = bias[c + 1];
                v0 += b0; v1 += b1; v2 += b0; v3 += b1;
            }
            if (EPI == EPI_BIAS_RES) {
                float2 ra = *(const float2*)(R + (size_t)r0 * ldres + c);
                float2 rb = *(const float2*)(R + (size_t)r1 * ldres + c);
                v0 += ra.x; v1 += ra.y; v2 += rb.x; v3 += rb.y;
            }
            if (EPI == EPI_GELU) {
                v0 = gelu_f(v0); v1 = gelu_f(v1);
                v2 = gelu_f(v2); v3 = gelu_f(v3);
            }
            if (EPI == EPI_EXP) {
                v0 = (c     <= r0) ? __expf(v0 * scale) : 0.f;
                v1 = (c + 1 <= r0) ? __expf(v1 * scale) : 0.f;
                v2 = (c     <= r1) ? __expf(v2 * scale) : 0.f;
                v3 = (c + 1 <= r1) ? __expf(v3 * scale) : 0.f;
            }
            if (EPI == EPI_PV) {
                float i0 = 1.f / g_rsum[(size_t)z * SS + r0];
                float i1 = 1.f / g_rsum[(size_t)z * SS + r1];
                v0 *= i0; v1 *= i0; v2 *= i1; v3 *= i1;
            }
            if (C_F32) {
                float* Cf = (float*)Cc + cBase;
                float2 oa = {v0, v1}, ob = {v2, v3};
                *(float2*)(Cf + (size_t)r0 * ldc + c) = oa;
                *(float2*)(Cf + (size_t)r1 * ldc + c) = ob;
            } else {
                __half* Ch = (__half*)Cc + cBase;
                __half2 ha = __floats2half2_rn(v0, v1);
                __half2 hb = __floats2half2_rn(v2, v3);
                *(__half2*)(Ch + (size_t)r0 * ldc + c) = ha;
                *(__half2*)(Ch + (size_t)r1 * ldc + c) = hb;
                if (EPI == EPI_EXP) {
                    float2 fa = __half22float2(ha);
                    float2 fb = __half22float2(hb);
                    s0[mf] += fa.x + fa.y;
                    s1[mf] += fb.x + fb.y;
                }
            }
        }
    }

    if (EPI == EPI_EXP) {
#pragma unroll
        for (int mf = 0; mf < MF; mf++) {
            s0[mf] += __shfl_xor_sync(0xffffffffu, s0[mf], 1);
            s0[mf] += __shfl_xor_sync(0xffffffffu, s0[mf], 2);
            s1[mf] += __shfl_xor_sync(0xffffffffu, s1[mf], 1);
            s1[mf] += __shfl_xor_sync(0xffffffffu, s1[mf], 2);
            if (tig == 0) {
                rowp[wnIdx][wm + mf * 16 + g    ] = s0[mf];
                rowp[wnIdx][wm + mf * 16 + g + 8] = s1[mf];
            }
        }
        __syncthreads();
        if (tid < BM) {
            float t = 0.f;
#pragma unroll
            for (int w = 0; w < WARPS_N; w++) t += rowp[w][tid];
            g_psum[((size_t)z * SS + bm + tid) * 8 + blockIdx.x] = t;
        }
    }
}

// ---------------------------------------------------------------------------
// Convert ALL fp32 weights to half into g_w in one launch.
// Regions (float4 units): w_in 768K, w_out 256K, w_fc 1M, w_proj 1M = 3M total.
// ---------------------------------------------------------------------------
__global__ __launch_bounds__(256)
void cvt_w_kernel(const float* __restrict__ w_in, const float* __restrict__ w_out,
                  const float* __restrict__ w_fc, const float* __restrict__ w_proj)
{
    int i = blockIdx.x * 256 + threadIdx.x;     // float4 index, < 3M
    const float* src;
    long dst;
    int local;
    if (i < 768 * 1024)            { src = w_in;   local = i;               dst = WOFF_IN; }
    else if (i < 1024 * 1024)      { src = w_out;  local = i - 768 * 1024;  dst = WOFF_OUT; }
    else if (i < 2048 * 1024)      { src = w_fc;   local = i - 1024 * 1024; dst = WOFF_FC; }
    else                           { src = w_proj; local = i - 2048 * 1024; dst = WOFF_PROJ; }
    float4 v = ((const float4*)src)[local];
    __half2 a = __floats2half2_rn(v.x, v.y);
    __half2 b = __floats2half2_rn(v.z, v.w);
    *(__half2*)(g_w + dst + (size_t)local * 4)     = a;
    *(__half2*)(g_w + dst + (size_t)local * 4 + 2) = b;
}

// ---------------------------------------------------------------------------
// Reduce per-tile partial sums -> row sums.
// ---------------------------------------------------------------------------
__global__ __launch_bounds__(256)
void reduce_psum_kernel()
{
    int r = blockIdx.x * 256 + threadIdx.x;
    int qr = r & (SS - 1);
    int nt = (qr >> 7) + 1;
    float s = 0.f;
    for (int t = 0; t < nt; t++) s += g_psum[(size_t)r * 8 + t];
    g_rsum[r] = s;
}

// ---------------------------------------------------------------------------
// att_weights[b,q,c] = (1/H) * sum_h probs[b,h,q,c] / rsum[b,h,q]
// ---------------------------------------------------------------------------
__global__ __launch_bounds__(256)
void mean_heads_kernel(float* __restrict__ out)
{
    int b = blockIdx.x >> 10;
    int q = blockIdx.x & (SS - 1);
    int t = threadIdx.x;

    __shared__ float inv[HH];
    if (t < HH) inv[t] = 1.f / g_rsum[((size_t)(b * HH + t)) * SS + q];
    __syncthreads();

    int KC4 = (q >> 2) + 1;
    float4 acc = {0.f, 0.f, 0.f, 0.f};
    if (t < KC4) {
#pragma unroll
        for (int h = 0; h < HH; h++) {
            const __half* p = g_probs + (((size_t)(b * HH + h)) * SS + q) * SS + t * 4;
            __half2 pa = *(const __half2*)p;
            __half2 pb = *(const __half2*)(p + 2);
            float2 fa = __half22float2(pa);
            float2 fb = __half22float2(pb);
            float iv = inv[h];
            acc.x += fa.x * iv; acc.y += fa.y * iv;
            acc.z += fb.x * iv; acc.w += fb.y * iv;
        }
        const float ih = 1.f / HH;
        acc.x *= ih; acc.y *= ih; acc.z *= ih; acc.w *= ih;
    }
    *(float4*)(out + ((size_t)(b * SS + q)) * SS + t * 4) = acc;
}

// ---------------------------------------------------------------------------
// LayerNorm: fp32 in (external x or g_x1), half out (GEMM operand).
// ---------------------------------------------------------------------------
__global__ __launch_bounds__(256)
void ln_kernel(const float* __restrict__ xx, int xid,
               const float* __restrict__ g, const float* __restrict__ bt,
               int outid)
{
    const float* x = resolve_f(xx, xid);
    __half* out = (__half*)scratch_ptr(outid);
    int row = blockIdx.x;
    const float* xr = x + (size_t)row * EE;
    int t = threadIdx.x;
    float4 v = *(const float4*)(xr + t * 4);
    float s  = v.x + v.y + v.z + v.w;
    float sq = v.x * v.x + v.y * v.y + v.z * v.z + v.w * v.w;
#pragma unroll
    for (int o = 16; o; o >>= 1) {
        s  += __shfl_xor_sync(0xffffffffu, s, o);
        sq += __shfl_xor_sync(0xffffffffu, sq, o);
    }
    __shared__ float ss[8], sqs[8];
    __shared__ float mu_s, rs_s;
    int w = t >> 5;
    if ((t & 31) == 0) { ss[w] = s; sqs[w] = sq; }
    __syncthreads();
    if (t == 0) {
        float S1 = 0.f, S2 = 0.f;
        for (int i = 0; i < 8; i++) { S1 += ss[i]; S2 += sqs[i]; }
        float mu  = S1 * (1.f / EE);
        float var = S2 * (1.f / EE) - mu * mu;
        mu_s = mu;
        rs_s = rsqrtf(var + 1e-5f);
    }
    __syncthreads();
    float mu = mu_s, rs = rs_s;
    float4 g4 = *(const float4*)(g + t * 4);
    float4 b4 = *(const float4*)(bt + t * 4);
    __half2 oa = __floats2half2_rn((v.x - mu) * rs * g4.x + b4.x,
                                   (v.y - mu) * rs * g4.y + b4.y);
    __half2 ob = __floats2half2_rn((v.z - mu) * rs * g4.z + b4.z,
                                   (v.w - mu) * rs * g4.w + b4.w);
    *(__half2*)(out + (size_t)row * EE + t * 4)     = oa;
    *(__half2*)(out + (size_t)row * EE + t * 4 + 2) = ob;
}

// ---------------------------------------------------------------------------
// kernel_launch
// Inputs: x, causal_mask, ln1_g, ln1_b, ln2_g, ln2_b,
//   w_in, b_in, w_out, b_out, w_fc, b_fc, w_proj, b_proj
// Output: [x (4096*1024 f32)] then [att_weights (4*1024*1024 f32)]
// ---------------------------------------------------------------------------
extern "C" void kernel_launch(void* const* d_in, const int* in_sizes, int n_in,
                              void* d_out, int out_size)
{
    const float* x     = (const float*)d_in[0];
    const float* ln1g  = (const float*)d_in[2];
    const float* ln1b  = (const float*)d_in[3];
    const float* ln2g  = (const float*)d_in[4];
    const float* ln2b  = (const float*)d_in[5];
    const float* w_in  = (const float*)d_in[6];
    const float* b_in  = (const float*)d_in[7];
    const float* w_out = (const float*)d_in[8];
    const float* b_out = (const float*)d_in[9];
    const float* w_fc  = (const float*)d_in[10];
    const float* b_fc  = (const float*)d_in[11];
    const float* w_proj= (const float*)d_in[12];
    const float* b_proj= (const float*)d_in[13];

    float* outx = (float*)d_out;
    float* outw = outx + (size_t)NTOK * EE;

    const float scale = 0.125f; // 1/sqrt(64)

    // Scratch ids: 0=g_h 1=g_qkv 2=g_probs 3=g_att 4=g_x1 5=g_h2 6=g_fc 7=g_w

    // 0) convert all weights to half (one launch, 3M float4s)
    cvt_w_kernel<<<3 * 1024 * 1024 / 256, 256>>>(w_in, w_out, w_fc, w_proj);

    // 1) h = LN1(x)  (half out)
    ln_kernel<<<NTOK, 256>>>(x, -1, ln1g, ln1b, 0);

    // 2) qkv = half(h @ w_in^T + b_in)    [4096 x 3072]
    mma_gemm<128, 128, 2, 4, EPI_BIAS, true, false>
        <<<dim3(3 * EE / 128, NTOK / 128, 1), 256>>>(
        0, 0,  7, WOFF_IN,  nullptr, 1,
        EE, EE, EE, 3 * EE, b_in, nullptr, -1, 0,
        0, 0, 0, 0, 0, 0, 1, 0.f);

    // 3) probs = half(exp(scale * q k^T)) masked + partial row sums (batched b,h)
    mma_gemm<128, 128, 2, 4, EPI_EXP, true, false>
        <<<dim3(SS / 128, SS / 128, BB * HH), 256>>>(
        1, 0,  1, EE,  nullptr, 2,
        DH, 3 * EE, 3 * EE, SS, nullptr, nullptr, -1, 0,
        (long)SS * 3 * EE, DH, (long)SS * 3 * EE, DH,
        (long)HH * SS * SS, (long)SS * SS, HH, scale);

    // 4) row sums
    reduce_psum_kernel<<<BB * HH * SS / 256, 256>>>();

    // 5) att_weights = mean over heads of normalized probs
    mean_heads_kernel<<<BB * SS, 256>>>(outw);

    // 6) att = half((probs @ v) / rsum)   (batched b,h; triangular K)
    mma_gemm<128, 64, 4, 2, EPI_PV, false, true>
        <<<dim3(1, SS / 128, BB * HH), 256>>>(
        2, 0,  1, 2 * EE,  nullptr, 3,
        SS, SS, 3 * EE, EE, nullptr, nullptr, -1, 0,
        (long)HH * SS * SS, (long)SS * SS, (long)SS * 3 * EE, DH,
        (long)SS * EE, DH, HH, 0.f);

    // 7) x1 = x + att @ w_out^T + b_out   (fp32 out)
    mma_gemm<128, 128, 2, 4, EPI_BIAS_RES, true, false>
        <<<dim3(EE / 128, NTOK / 128, 1), 256>>>(
        3, 0,  7, WOFF_OUT,  nullptr, 4,
        EE, EE, EE, EE, b_out, x, -1, EE,
        0, 0, 0, 0, 0, 0, 1, 0.f);

    // 8) h2 = LN2(x1)  (half out)
    ln_kernel<<<NTOK, 256>>>(nullptr, 4, ln2g, ln2b, 5);

    // 9) fc = half(gelu(h2 @ w_fc^T + b_fc))   [4096 x 4096]
    mma_gemm<128, 128, 2, 4, EPI_GELU, true, false>
        <<<dim3(4 * EE / 128, NTOK / 128, 1), 256>>>(
        5, 0,  7, WOFF_FC,  nullptr, 6,
        EE, EE, EE, 4 * EE, b_fc, nullptr, -1, 0,
        0, 0, 0, 0, 0, 0, 1, 0.f);

    // 10) out_x = x1 + fc @ w_proj^T + b_proj   (fp32 out)
    mma_gemm<128, 128, 2, 4, EPI_BIAS_RES, true, false>
        <<<dim3(EE / 128, NTOK / 128, 1), 256>>>(
        6, 0,  7, WOFF_PROJ,  outx, -1,
        4 * EE, 4 * EE, 4 * EE, EE, b_proj, nullptr, 4, EE,
        0, 0, 0, 0, 0, 0, 1, 0.f);
}

// round 13
// speedup vs baseline: 2.4262x; 1.2339x over previous
#include <cuda_runtime.h>
#include <cuda_fp16.h>
#include <math.h>
#include <stdint.h>

// ---------------------------------------------------------------------------
// Problem constants: B=4, S=1024, E=1024, H=16, DH=64
// ---------------------------------------------------------------------------
#define BB   4
#define SS   1024
#define EE   1024
#define HH   16
#define DH   64
#define NTOK (BB * SS)          // 4096 rows

// ---------------------------------------------------------------------------
// Scratch (static device globals; no allocation allowed anywhere)
// ---------------------------------------------------------------------------
__device__ __half g_h    [(size_t)NTOK * EE];
__device__ __half g_qkv  [(size_t)NTOK * 3 * EE];
__device__ __half g_probs[(size_t)BB * HH * SS * SS];   // unnormalized exp scores (half)
__device__ __half g_att  [(size_t)NTOK * EE];
__device__ float  g_x1   [(size_t)NTOK * EE];           // residual chain stays fp32
__device__ __half g_h2   [(size_t)NTOK * EE];
__device__ __half g_fc   [(size_t)NTOK * 4 * EE];
__device__ __half g_w    [(size_t)12 * 1024 * 1024];    // half weights
__device__ float  g_psum [(size_t)BB * HH * SS * 8];
__device__ float  g_rsum [(size_t)BB * HH * SS];

// g_w offsets (elements)
#define WOFF_IN   0L
#define WOFF_OUT  (3L * 1024 * 1024)
#define WOFF_FC   (4L * 1024 * 1024)
#define WOFF_PROJ (8L * 1024 * 1024)

__device__ __forceinline__ void* scratch_ptr(int id) {
    switch (id) {
        case 0:  return (void*)g_h;
        case 1:  return (void*)g_qkv;
        case 2:  return (void*)g_probs;
        case 3:  return (void*)g_att;
        case 4:  return (void*)g_x1;
        case 5:  return (void*)g_h2;
        case 7:  return (void*)g_w;
        default: return (void*)g_fc;
    }
}
__device__ __forceinline__ const __half* resolve_h(int id, long off) {
    return (const __half*)scratch_ptr(id) + off;
}
__device__ __forceinline__ const float* resolve_f(const float* ext, int id) {
    return id >= 0 ? (const float*)scratch_ptr(id) : ext;
}

__device__ __forceinline__ float gelu_f(float v) {
    const float c = 0.7978845608028654f;
    float t = tanhf(c * (v + 0.044715f * v * v * v));
    return 0.5f * v * (1.f + t);
}

// fp16 tensor-core mma: m16n8k16, fp32 accumulate
__device__ __forceinline__ void mma_f16(float* c, const uint32_t* a, const uint32_t* b) {
    asm volatile(
        "mma.sync.aligned.m16n8k16.row.col.f32.f16.f16.f32 "
        "{%0,%1,%2,%3}, {%4,%5,%6,%7}, {%8,%9}, {%0,%1,%2,%3};"
        : "+f"(c[0]), "+f"(c[1]), "+f"(c[2]), "+f"(c[3])
        : "r"(a[0]), "r"(a[1]), "r"(a[2]), "r"(a[3]), "r"(b[0]), "r"(b[1]));
}

__device__ __forceinline__ void ldsm4(uint32_t* r, uint32_t a) {
    asm volatile("ldmatrix.sync.aligned.m8n8.x4.shared.b16 {%0,%1,%2,%3}, [%4];"
        : "=r"(r[0]), "=r"(r[1]), "=r"(r[2]), "=r"(r[3]) : "r"(a));
}
__device__ __forceinline__ void ldsm4t(uint32_t* r, uint32_t a) {
    asm volatile("ldmatrix.sync.aligned.m8n8.x4.trans.shared.b16 {%0,%1,%2,%3}, [%4];"
        : "=r"(r[0]), "=r"(r[1]), "=r"(r[2]), "=r"(r[3]) : "r"(a));
}

__device__ __forceinline__ void cp16(void* dst, const void* src) {
    uint32_t d = (uint32_t)__cvta_generic_to_shared(dst);
    asm volatile("cp.async.ca.shared.global [%0], [%1], 16;\n" :: "r"(d), "l"(src));
}
__device__ __forceinline__ void cp_commit() {
    asm volatile("cp.async.commit_group;\n");
}
template <int N>
__device__ __forceinline__ void cp_wait() {
    asm volatile("cp.async.wait_group %0;\n" :: "n"(N));
}

enum { EPI_BIAS = 1, EPI_BIAS_RES = 2, EPI_GELU = 3, EPI_EXP = 4, EPI_PV = 5 };

// ---------------------------------------------------------------------------
// fp16 tensor-core GEMM, cp.async double buffered (BK=64), fp32 accumulate.
//   B_NT=true : B stored [N,K] row-major (C = A * B^T)  — ldmatrix
//   B_NT=false: B stored [K,N] row-major (C = A * B)    — ldmatrix.trans
// Block tile BM x BN x 64(halves), 256 threads = WARPS_M x WARPS_N warps.
// Dynamic smem: [2][BM][AKP] A, [2][BD1][BD2] B, rowp.
// EPI_EXP: p = half(exp(scale*s)) masked + per-tile row sums; masked tiles exit.
// EPI_PV : /rsum, TRI_K truncation.
// ---------------------------------------------------------------------------
template <int BM, int BN, int WARPS_M, int WARPS_N, int EPI, bool B_NT, bool TRI_K>
__global__ __launch_bounds__(256)
void mma_gemm(int Aid, long Aoff, int Bid, long Boff,
              void* __restrict__ Cx, int Cid,
              int K, int lda, int ldb, int ldc,
              const float* __restrict__ bias,
              const float* __restrict__ Rx, int Rid, int ldres,
              long aOuter, long aInner, long bOuter, long bInner,
              long cOuter, long cInner, int Hdim, float scale)
{
    constexpr int BK  = 64;                 // halves per K tile
    constexpr int AKP = BK + 8;             // 72-half (144B) rows: conflict-free
    constexpr int WM = BM / WARPS_M, WN = BN / WARPS_N;
    constexpr int MF = WM / 16, NF = WN / 8;
    constexpr int BD1 = B_NT ? BN : BK;
    constexpr int BD2 = B_NT ? AKP : (BN + 8);
    constexpr int RP2 = BM;
    constexpr bool C_F32 = (EPI == EPI_BIAS_RES);

    int bm = blockIdx.y * BM, bn = blockIdx.x * BN;
    if (EPI == EPI_EXP && bn >= bm + BM) return;

    const __half* A = resolve_h(Aid, Aoff);
    const __half* B = resolve_h(Bid, Boff);
    char* Cc = (Cid >= 0) ? (char*)scratch_ptr(Cid) : (char*)Cx;

    int z  = blockIdx.z;
    int zo = z / Hdim, zi = z - zo * Hdim;
    A += (size_t)zo * aOuter + (size_t)zi * aInner;
    B += (size_t)zo * bOuter + (size_t)zi * bInner;
    size_t cBase = (size_t)zo * cOuter + (size_t)zi * cInner;

    extern __shared__ __align__(16) char smraw[];
    typedef __half ARow[BM][AKP];
    typedef __half BRow[BD1][BD2];
    ARow* As = (ARow*)smraw;                                  // [2][BM][AKP]
    BRow* Bs = (BRow*)(smraw + 4 * BM * AKP);                 // [2][BD1][BD2]
    float (*rowp)[RP2] = (float(*)[RP2])(smraw + 4 * BM * AKP + 4 * BD1 * BD2);

    int tid  = threadIdx.x;
    int wid  = tid >> 5, lane = tid & 31;
    int g    = lane >> 2, tig = lane & 3;
    int wm   = (wid / WARPS_N) * WM;
    int wn   = (wid % WARPS_N) * WN;
    int wnIdx = wid % WARPS_N;

    const __half* Ag = A + (size_t)bm * lda;
    const __half* Bg = B_NT ? (B + (size_t)bn * ldb) : B;

    int Kend = TRI_K ? min(K, bm + BM) : K;
    int T = Kend / BK;

    float acc[MF][NF][4] = {};

    uint32_t smA = (uint32_t)__cvta_generic_to_shared(&As[0][0][0]);
    uint32_t smB = (uint32_t)__cvta_generic_to_shared(&Bs[0][0][0]);
    const uint32_t aBuf = (uint32_t)(BM * AKP * 2);
    const uint32_t bBuf = (uint32_t)(BD1 * BD2 * 2);
    // A frag: lane -> row (lane&15), k-offset (lane>>4)*8
    uint32_t aAddr = smA + (uint32_t)(((wm + (lane & 15)) * AKP + ((lane >> 4) * 8)) * 2);
    // B frag (B_NT): lane -> n row (lane&7)+(lane>>4)*8, k-offset ((lane>>3)&1)*8
    uint32_t bAddr = smB + (uint32_t)(((wn + (lane & 7) + ((lane >> 4) * 8)) * AKP
                                       + (((lane >> 3) & 1) * 8)) * 2);
    // B frag (trans, [K,N]): octets: k row (lane&7) + ((lane>>3)&1)*8, n col (lane>>4)*8
    uint32_t bAddrT = smB + (uint32_t)((((lane & 7) + ((lane >> 3) & 1) * 8) * BD2
                                       + wn + ((lane >> 4) * 8)) * 2);

    auto loadA = [&](int st, int k0) {
#pragma unroll
        for (int i = 0; i < BM / 32; i++) {
            int c = tid + i * 256;
            int m = c >> 3, q = c & 7;
            cp16(&As[st][m][q * 8], Ag + (size_t)m * lda + k0 + q * 8);
        }
    };
    auto loadB = [&](int st, int k0) {
        if (B_NT) {
#pragma unroll
            for (int i = 0; i < BN / 32; i++) {
                int c = tid + i * 256;
                int n = c >> 3, q = c & 7;
                cp16(&Bs[st][n][q * 8], Bg + (size_t)n * ldb + k0 + q * 8);
            }
        } else {
            constexpr int CPR = BN / 8;
#pragma unroll
            for (int i = 0; i < (BK * CPR) / 256; i++) {
                int c = tid + i * 256;
                int k = c / CPR, n8 = c % CPR;
                cp16(&Bs[st][k][n8 * 8], B + (size_t)(k0 + k) * ldb + bn + n8 * 8);
            }
        }
    };

    loadA(0, 0); loadB(0, 0); cp_commit();

    int buf = 0;
    for (int it = 0; it < T; it++) {
        if (it + 1 < T) {
            loadA(buf ^ 1, (it + 1) * BK);
            loadB(buf ^ 1, (it + 1) * BK);
            cp_commit();
            cp_wait<1>();
        } else {
            cp_wait<0>();
        }
        __syncthreads();

        uint32_t aB = aAddr + buf * aBuf;
        uint32_t bB = (B_NT ? bAddr : bAddrT) + buf * bBuf;

#pragma unroll
        for (int kk = 0; kk < BK; kk += 16) {
            uint32_t af[MF][4], bf[NF][2];
#pragma unroll
            for (int mf = 0; mf < MF; mf++)
                ldsm4(af[mf], aB + (uint32_t)((mf * 16 * AKP + kk) * 2));
            if (B_NT) {
#pragma unroll
                for (int nfp = 0; nfp < NF / 2; nfp++) {
                    uint32_t bq[4];
                    ldsm4(bq, bB + (uint32_t)((nfp * 16 * AKP + kk) * 2));
                    bf[nfp * 2    ][0] = bq[0]; bf[nfp * 2    ][1] = bq[1];
                    bf[nfp * 2 + 1][0] = bq[2]; bf[nfp * 2 + 1][1] = bq[3];
                }
            } else {
#pragma unroll
                for (int nfp = 0; nfp < NF / 2; nfp++) {
                    uint32_t bq[4];
                    ldsm4t(bq, bB + (uint32_t)((kk * BD2 + nfp * 16) * 2));
                    bf[nfp * 2    ][0] = bq[0]; bf[nfp * 2    ][1] = bq[1];
                    bf[nfp * 2 + 1][0] = bq[2]; bf[nfp * 2 + 1][1] = bq[3];
                }
            }
#pragma unroll
            for (int mf = 0; mf < MF; mf++)
#pragma unroll
                for (int nf = 0; nf < NF; nf++)
                    mma_f16(acc[mf][nf], af[mf], bf[nf]);
        }
        __syncthreads();
        buf ^= 1;
    }

    // ---- epilogue ----
    const float* R = (EPI == EPI_BIAS_RES) ? resolve_f(Rx, Rid) : nullptr;

    float s0[MF], s1[MF];
    if (EPI == EPI_EXP) {
#pragma unroll
        for (int mf = 0; mf < MF; mf++) { s0[mf] = 0.f; s1[mf] = 0.f; }
    }

#pragma unroll
    for (int mf = 0; mf < MF; mf++) {
#pragma unroll
        for (int nf = 0; nf < NF; nf++) {
            int r0 = bm + wm + mf * 16 + g;
            int r1 = r0 + 8;
            int c  = bn + wn + nf * 8 + tig * 2;
            float v0 = acc[mf][nf][0], v1 = acc[mf][nf][1];
            float v2 = acc[mf][nf][2], v3 = acc[mf][nf][3];
            if (EPI == EPI_BIAS || EPI == EPI_BIAS_RES || EPI == EPI_GELU) {
                float b0 = bias[c], b1 = bias[c + 1];
                v0 += b0; v1 += b1; v2 += b0; v3 += b1;
            }
            if (EPI == EPI_BIAS_RES) {
                float2 ra = *(const float2*)(R + (size_t)r0 * ldres + c);
                float2 rb = *(const float2*)(R + (size_t)r1 * ldres + c);
                v0 += ra.x; v1 += ra.y; v2 += rb.x; v3 += rb.y;
            }
            if (EPI == EPI_GELU) {
                v0 = gelu_f(v0); v1 = gelu_f(v1);
                v2 = gelu_f(v2); v3 = gelu_f(v3);
            }
            if (EPI == EPI_EXP) {
                v0 = (c     <= r0) ? __expf(v0 * scale) : 0.f;
                v1 = (c + 1 <= r0) ? __expf(v1 * scale) : 0.f;
                v2 = (c     <= r1) ? __expf(v2 * scale) : 0.f;
                v3 = (c + 1 <= r1) ? __expf(v3 * scale) : 0.f;
            }
            if (EPI == EPI_PV) {
                float i0 = 1.f / g_rsum[(size_t)z * SS + r0];
                float i1 = 1.f / g_rsum[(size_t)z * SS + r1];
                v0 *= i0; v1 *= i0; v2 *= i1; v3 *= i1;
            }
            if (C_F32) {
                float* Cf = (float*)Cc + cBase;
                float2 oa = {v0, v1}, ob = {v2, v3};
                *(float2*)(Cf + (size_t)r0 * ldc + c) = oa;
                *(float2*)(Cf + (size_t)r1 * ldc + c) = ob;
            } else {
                __half* Ch = (__half*)Cc + cBase;
                __half2 ha = __floats2half2_rn(v0, v1);
                __half2 hb = __floats2half2_rn(v2, v3);
                *(__half2*)(Ch + (size_t)r0 * ldc + c) = ha;
                *(__half2*)(Ch + (size_t)r1 * ldc + c) = hb;
                if (EPI == EPI_EXP) {
                    float2 fa = __half22float2(ha);
                    float2 fb = __half22float2(hb);
                    s0[mf] += fa.x + fa.y;
                    s1[mf] += fb.x + fb.y;
                }
            }
        }
    }

    if (EPI == EPI_EXP) {
#pragma unroll
        for (int mf = 0; mf < MF; mf++) {
            s0[mf] += __shfl_xor_sync(0xffffffffu, s0[mf], 1);
            s0[mf] += __shfl_xor_sync(0xffffffffu, s0[mf], 2);
            s1[mf] += __shfl_xor_sync(0xffffffffu, s1[mf], 1);
            s1[mf] += __shfl_xor_sync(0xffffffffu, s1[mf], 2);
            if (tig == 0) {
                rowp[wnIdx][wm + mf * 16 + g    ] = s0[mf];
                rowp[wnIdx][wm + mf * 16 + g + 8] = s1[mf];
            }
        }
        __syncthreads();
        if (tid < BM) {
            float t = 0.f;
#pragma unroll
            for (int w = 0; w < WARPS_N; w++) t += rowp[w][tid];
            g_psum[((size_t)z * SS + bm + tid) * 8 + blockIdx.x] = t;
        }
    }
}

// dynamic smem sizes (bytes)
#define SMEM_NT (4 * 128 * 72 + 4 * 128 * 72 + 4 * 128 * 4)   // 75776
#define SMEM_PV (4 * 128 * 72 + 4 * 64 * 72 + 4 * 128 * 4)    // 57344

// ---------------------------------------------------------------------------
// Convert ALL fp32 weights to half into g_w in one launch.
// ---------------------------------------------------------------------------
__global__ __launch_bounds__(256)
void cvt_w_kernel(const float* __restrict__ w_in, const float* __restrict__ w_out,
                  const float* __restrict__ w_fc, const float* __restrict__ w_proj)
{
    int i = blockIdx.x * 256 + threadIdx.x;     // float4 index, < 3M
    const float* src;
    long dst;
    int local;
    if (i < 768 * 1024)            { src = w_in;   local = i;               dst = WOFF_IN; }
    else if (i < 1024 * 1024)      { src = w_out;  local = i - 768 * 1024;  dst = WOFF_OUT; }
    else if (i < 2048 * 1024)      { src = w_fc;   local = i - 1024 * 1024; dst = WOFF_FC; }
    else                           { src = w_proj; local = i - 2048 * 1024; dst = WOFF_PROJ; }
    float4 v = ((const float4*)src)[local];
    __half2 a = __floats2half2_rn(v.x, v.y);
    __half2 b = __floats2half2_rn(v.z, v.w);
    *(__half2*)(g_w + dst + (size_t)local * 4)     = a;
    *(__half2*)(g_w + dst + (size_t)local * 4 + 2) = b;
}

// ---------------------------------------------------------------------------
// Reduce per-tile partial sums -> row sums.
// ---------------------------------------------------------------------------
__global__ __launch_bounds__(256)
void reduce_psum_kernel()
{
    int r = blockIdx.x * 256 + threadIdx.x;
    int qr = r & (SS - 1);
    int nt = (qr >> 7) + 1;
    float s = 0.f;
    for (int t = 0; t < nt; t++) s += g_psum[(size_t)r * 8 + t];
    g_rsum[r] = s;
}

// ---------------------------------------------------------------------------
// att_weights[b,q,c] = (1/H) * sum_h probs[b,h,q,c] / rsum[b,h,q]
// ---------------------------------------------------------------------------
__global__ __launch_bounds__(256)
void mean_heads_kernel(float* __restrict__ out)
{
    int b = blockIdx.x >> 10;
    int q = blockIdx.x & (SS - 1);
    int t = threadIdx.x;

    __shared__ float inv[HH];
    if (t < HH) inv[t] = 1.f / g_rsum[((size_t)(b * HH + t)) * SS + q];
    __syncthreads();

    int KC4 = (q >> 2) + 1;
    float4 acc = {0.f, 0.f, 0.f, 0.f};
    if (t < KC4) {
#pragma unroll
        for (int h = 0; h < HH; h++) {
            const __half* p = g_probs + (((size_t)(b * HH + h)) * SS + q) * SS + t * 4;
            __half2 pa = *(const __half2*)p;
            __half2 pb = *(const __half2*)(p + 2);
            float2 fa = __half22float2(pa);
            float2 fb = __half22float2(pb);
            float iv = inv[h];
            acc.x += fa.x * iv; acc.y += fa.y * iv;
            acc.z += fb.x * iv; acc.w += fb.y * iv;
        }
        const float ih = 1.f / HH;
        acc.x *= ih; acc.y *= ih; acc.z *= ih; acc.w *= ih;
    }
    *(float4*)(out + ((size_t)(b * SS + q)) * SS + t * 4) = acc;
}

// ---------------------------------------------------------------------------
// LayerNorm: fp32 in (external x or g_x1), half out (GEMM operand).
// ---------------------------------------------------------------------------
__global__ __launch_bounds__(256)
void ln_kernel(const float* __restrict__ xx, int xid,
               const float* __restrict__ g, const float* __restrict__ bt,
               int outid)
{
    const float* x = resolve_f(xx, xid);
    __half* out = (__half*)scratch_ptr(outid);
    int row = blockIdx.x;
    const float* xr = x + (size_t)row * EE;
    int t = threadIdx.x;
    float4 v = *(const float4*)(xr + t * 4);
    float s  = v.x + v.y + v.z + v.w;
    float sq = v.x * v.x + v.y * v.y + v.z * v.z + v.w * v.w;
#pragma unroll
    for (int o = 16; o; o >>= 1) {
        s  += __shfl_xor_sync(0xffffffffu, s, o);
        sq += __shfl_xor_sync(0xffffffffu, sq, o);
    }
    __shared__ float ss[8], sqs[8];
    __shared__ float mu_s, rs_s;
    int w = t >> 5;
    if ((t & 31) == 0) { ss[w] = s; sqs[w] = sq; }
    __syncthreads();
    if (t == 0) {
        float S1 = 0.f, S2 = 0.f;
        for (int i = 0; i < 8; i++) { S1 += ss[i]; S2 += sqs[i]; }
        float mu  = S1 * (1.f / EE);
        float var = S2 * (1.f / EE) - mu * mu;
        mu_s = mu;
        rs_s = rsqrtf(var + 1e-5f);
    }
    __syncthreads();
    float mu = mu_s, rs = rs_s;
    float4 g4 = *(const float4*)(g + t * 4);
    float4 b4 = *(const float4*)(bt + t * 4);
    __half2 oa = __floats2half2_rn((v.x - mu) * rs * g4.x + b4.x,
                                   (v.y - mu) * rs * g4.y + b4.y);
    __half2 ob = __floats2half2_rn((v.z - mu) * rs * g4.z + b4.z,
                                   (v.w - mu) * rs * g4.w + b4.w);
    *(__half2*)(out + (size_t)row * EE + t * 4)     = oa;
    *(__half2*)(out + (size_t)row * EE + t * 4 + 2) = ob;
}

// ---------------------------------------------------------------------------
// kernel_launch
// Inputs: x, causal_mask, ln1_g, ln1_b, ln2_g, ln2_b,
//   w_in, b_in, w_out, b_out, w_fc, b_fc, w_proj, b_proj
// Output: [x (4096*1024 f32)] then [att_weights (4*1024*1024 f32)]
// ---------------------------------------------------------------------------
extern "C" void kernel_launch(void* const* d_in, const int* in_sizes, int n_in,
                              void* d_out, int out_size)
{
    const float* x     = (const float*)d_in[0];
    const float* ln1g  = (const float*)d_in[2];
    const float* ln1b  = (const float*)d_in[3];
    const float* ln2g  = (const float*)d_in[4];
    const float* ln2b  = (const float*)d_in[5];
    const float* w_in  = (const float*)d_in[6];
    const float* b_in  = (const float*)d_in[7];
    const float* w_out = (const float*)d_in[8];
    const float* b_out = (const float*)d_in[9];
    const float* w_fc  = (const float*)d_in[10];
    const float* b_fc  = (const float*)d_in[11];
    const float* w_proj= (const float*)d_in[12];
    const float* b_proj= (const float*)d_in[13];

    float* outx = (float*)d_out;
    float* outw = outx + (size_t)NTOK * EE;

    const float scale = 0.125f; // 1/sqrt(64)

    // Opt in to >48KB dynamic smem (idempotent; non-stream API)
    cudaFuncSetAttribute(mma_gemm<128, 128, 2, 4, EPI_BIAS, true, false>,
                         cudaFuncAttributeMaxDynamicSharedMemorySize, SMEM_NT);
    cudaFuncSetAttribute(mma_gemm<128, 128, 2, 4, EPI_EXP, true, false>,
                         cudaFuncAttributeMaxDynamicSharedMemorySize, SMEM_NT);
    cudaFuncSetAttribute(mma_gemm<128, 128, 2, 4, EPI_BIAS_RES, true, false>,
                         cudaFuncAttributeMaxDynamicSharedMemorySize, SMEM_NT);
    cudaFuncSetAttribute(mma_gemm<128, 128, 2, 4, EPI_GELU, true, false>,
                         cudaFuncAttributeMaxDynamicSharedMemorySize, SMEM_NT);
    cudaFuncSetAttribute(mma_gemm<128, 64, 4, 2, EPI_PV, false, true>,
                         cudaFuncAttributeMaxDynamicSharedMemorySize, SMEM_PV);

    // Scratch ids: 0=g_h 1=g_qkv 2=g_probs 3=g_att 4=g_x1 5=g_h2 6=g_fc 7=g_w

    // 0) convert all weights to half (one launch)
    cvt_w_kernel<<<3 * 1024 * 1024 / 256, 256>>>(w_in, w_out, w_fc, w_proj);

    // 1) h = LN1(x)  (half out)
    ln_kernel<<<NTOK, 256>>>(x, -1, ln1g, ln1b, 0);

    // 2) qkv = half(h @ w_in^T + b_in)    [4096 x 3072]
    mma_gemm<128, 128, 2, 4, EPI_BIAS, true, false>
        <<<dim3(3 * EE / 128, NTOK / 128, 1), 256, SMEM_NT>>>(
        0, 0,  7, WOFF_IN,  nullptr, 1,
        EE, EE, EE, 3 * EE, b_in, nullptr, -1, 0,
        0, 0, 0, 0, 0, 0, 1, 0.f);

    // 3) probs = half(exp(scale * q k^T)) masked + partial row sums (batched b,h)
    mma_gemm<128, 128, 2, 4, EPI_EXP, true, false>
        <<<dim3(SS / 128, SS / 128, BB * HH), 256, SMEM_NT>>>(
        1, 0,  1, EE,  nullptr, 2,
        DH, 3 * EE, 3 * EE, SS, nullptr, nullptr, -1, 0,
        (long)SS * 3 * EE, DH, (long)SS * 3 * EE, DH,
        (long)HH * SS * SS, (long)SS * SS, HH, scale);

    // 4) row sums
    reduce_psum_kernel<<<BB * HH * SS / 256, 256>>>();

    // 5) att_weights = mean over heads of normalized probs
    mean_heads_kernel<<<BB * SS, 256>>>(outw);

    // 6) att = half((probs @ v) / rsum)   (batched b,h; triangular K)
    mma_gemm<128, 64, 4, 2, EPI_PV, false, true>
        <<<dim3(1, SS / 128, BB * HH), 256, SMEM_PV>>>(
        2, 0,  1, 2 * EE,  nullptr, 3,
        SS, SS, 3 * EE, EE, nullptr, nullptr, -1, 0,
        (long)HH * SS * SS, (long)SS * SS, (long)SS * 3 * EE, DH,
        (long)SS * EE, DH, HH, 0.f);

    // 7) x1 = x + att @ w_out^T + b_out   (fp32 out)
    mma_gemm<128, 128, 2, 4, EPI_BIAS_RES, true, false>
        <<<dim3(EE / 128, NTOK / 128, 1), 256, SMEM_NT>>>(
        3, 0,  7, WOFF_OUT,  nullptr, 4,
        EE, EE, EE, EE, b_out, x, -1, EE,
        0, 0, 0, 0, 0, 0, 1, 0.f);

    // 8) h2 = LN2(x1)  (half out)
    ln_kernel<<<NTOK, 256>>>(nullptr, 4, ln2g, ln2b, 5);

    // 9) fc = half(gelu(h2 @ w_fc^T + b_fc))   [4096 x 4096]
    mma_gemm<128, 128, 2, 4, EPI_GELU, true, false>
        <<<dim3(4 * EE / 128, NTOK / 128, 1), 256, SMEM_NT>>>(
        5, 0,  7, WOFF_FC,  nullptr, 6,
        EE, EE, EE, 4 * EE, b_fc, nullptr, -1, 0,
        0, 0, 0, 0, 0, 0, 1, 0.f);

    // 10) out_x = x1 + fc @ w_proj^T + b_proj   (fp32 out)
    mma_gemm<128, 128, 2, 4, EPI_BIAS_RES, true, false>
        <<<dim3(EE / 128, NTOK / 128, 1), 256, SMEM_NT>>>(
        6, 0,  7, WOFF_PROJ,  outx, -1,
        4 * EE, 4 * EE, 4 * EE, EE, b_proj, nullptr, 4, EE,
        0, 0, 0, 0, 0, 0, 1, 0.f);
}